// round 7
// baseline (speedup 1.0000x reference)
#include <cuda_runtime.h>
#include <cuda_bf16.h>
#include <mma.h>
#include <cstdint>

using namespace nvcuda;

#define NU 100000
#define NI 50000
#define NN 150000
#define DD 64
#define EG 3200000
#define EU_ 1600000
#define EI_ 800000

// ---------------- device scratch ----------------
__device__ float g_cur[NN * DD];
__device__ float g_gnn[NN * DD];
__device__ float g_total[NN * DD];
__device__ float g_z[NN * 2 * DD];        // row = node*2 + metapath
__device__ float g_wsum[4];

// CSR for G
__device__ int    g_cntG[NN];
__device__ int    g_curG[NN];
__device__ int    g_rptrG[NN + 1];
__device__ float2 g_epayG[EG];            // {col_bits, val}

// CSR + degrees for HAN
#define HN (2 * NU + 2 * NI)
__device__ int g_dout[HN];
__device__ int g_din[HN];
__device__ int g_curH[HN];
__device__ int g_rptrH[2 * (NU + 1) + 2 * (NI + 1)];
__device__ int g_hpay[2 * EU_ + 2 * EI_];

// ---------------- zero counters ----------------
__global__ void __launch_bounds__(256) k_zero_cnt() {
    unsigned i = blockIdx.x * 256u + threadIdx.x;
    if (i < NN) { g_cntG[i] = 0; g_curG[i] = 0; }
    if (i < HN) { g_dout[i] = 0; g_din[i] = 0; g_curH[i] = 0; }
    if (i < 4u) g_wsum[i] = 0.f;
}

// ---------------- init ----------------
__global__ void __launch_bounds__(256) k_init(const float* __restrict__ fu,
                                              const float* __restrict__ fi) {
    unsigned i = blockIdx.x * 256u + threadIdx.x;
    if (i < NU * DD) {
        float v = fu[i];
        g_cur[i] = v; g_total[i] = v;
    } else if (i < NN * DD) {
        float v = fi[i - NU * DD];
        g_cur[i] = v; g_total[i] = v;
    }
}

// ---------------- CSR build ----------------
__global__ void __launch_bounds__(256) k_histG(const int* __restrict__ G) {
    unsigned e = blockIdx.x * 256u + threadIdx.x;
    if (e >= EG) return;
    atomicAdd(&g_cntG[__ldg(G + e)], 1);
}

__global__ void __launch_bounds__(256) k_histH(const int* __restrict__ edges, int E2,
                                               int n, int base) {
    unsigned t = blockIdx.x * 256u + threadIdx.x;
    if (t >= 2u * (unsigned)E2) return;
    int m = (t >= (unsigned)E2) ? 1 : 0;
    int e = (int)t - m * E2;
    int src = __ldg(edges + (size_t)m * 2 * E2 + e);
    int dst = __ldg(edges + (size_t)m * 2 * E2 + E2 + e);
    atomicAdd(&g_dout[base + m * n + src], 1);
    atomicAdd(&g_din[base + m * n + dst], 1);
}

__global__ void __launch_bounds__(1024) k_scan() {
    const int* cnt; int* rptr; int n;
    switch (blockIdx.x) {
        case 0: cnt = g_cntG;              rptr = g_rptrG;                          n = NN; break;
        case 1: cnt = g_din;               rptr = g_rptrH;                          n = NU; break;
        case 2: cnt = g_din + NU;          rptr = g_rptrH + (NU + 1);               n = NU; break;
        case 3: cnt = g_din + 2 * NU;      rptr = g_rptrH + 2 * (NU + 1);           n = NI; break;
        default: cnt = g_din + 2 * NU + NI; rptr = g_rptrH + 2 * (NU + 1) + (NI + 1); n = NI; break;
    }
    __shared__ int wsum[32];
    __shared__ int s_carry;
    const int tid = threadIdx.x, lane = tid & 31, wid = tid >> 5;
    if (tid == 0) s_carry = 0;
    __syncthreads();
    for (int base = 0; base < n; base += 1024) {
        int i = base + tid;
        int v = (i < n) ? cnt[i] : 0;
        int x = v;
#pragma unroll
        for (int off = 1; off < 32; off <<= 1) {
            int y = __shfl_up_sync(0xffffffffu, x, off);
            if (lane >= off) x += y;
        }
        if (lane == 31) wsum[wid] = x;
        __syncthreads();
        if (wid == 0) {
            int s = wsum[lane];
#pragma unroll
            for (int off = 1; off < 32; off <<= 1) {
                int y = __shfl_up_sync(0xffffffffu, s, off);
                if (lane >= off) s += y;
            }
            wsum[lane] = s;
        }
        __syncthreads();
        int excl = x - v + (wid > 0 ? wsum[wid - 1] : 0) + s_carry;
        int ctot = wsum[31];
        if (i < n) rptr[i] = excl;
        __syncthreads();
        if (tid == 0) s_carry += ctot;
        __syncthreads();
    }
    if (tid == 0) rptr[n] = s_carry;
}

__global__ void __launch_bounds__(256) k_fillG(const int* __restrict__ G,
                                               const float* __restrict__ gv) {
    unsigned e = blockIdx.x * 256u + threadIdx.x;
    if (e >= EG) return;
    int row = __ldg(G + e);
    int col = __ldg(G + EG + e);
    float v = __ldg(gv + e);
    int pos = g_rptrG[row] + atomicAdd(&g_curG[row], 1);
    g_epayG[pos] = make_float2(__int_as_float(col), v);
}

__global__ void __launch_bounds__(256) k_fillH(const int* __restrict__ edges, int E2,
                                               int n, int base, int rbase, int paybase) {
    unsigned t = blockIdx.x * 256u + threadIdx.x;
    if (t >= 2u * (unsigned)E2) return;
    int m = (t >= (unsigned)E2) ? 1 : 0;
    int e = (int)t - m * E2;
    int src = __ldg(edges + (size_t)m * 2 * E2 + e);
    int dst = __ldg(edges + (size_t)m * 2 * E2 + E2 + e);
    const int* rptr = g_rptrH + rbase + m * (n + 1);
    int pos = rptr[dst] + atomicAdd(&g_curH[base + m * n + dst], 1);
    g_hpay[paybase + m * E2 + pos] = src;
}

// ---------------- DCCF: CSR SpMM ----------------
__global__ void __launch_bounds__(256) k_spmm_csr() {
    unsigned t = blockIdx.x * 256u + threadIdx.x;
    unsigned r = t >> 4;
    unsigned c = t & 15u;
    if (r >= NN) return;
    int s = g_rptrG[r], e = g_rptrG[r + 1];
    float4 acc = make_float4(0.f, 0.f, 0.f, 0.f);
    int i = s;
    for (; i + 2 <= e; i += 2) {
        float2 p0 = __ldg(&g_epayG[i]);
        float2 p1 = __ldg(&g_epayG[i + 1]);
        int c0 = __float_as_int(p0.x), c1 = __float_as_int(p1.x);
        float4 x0 = *(const float4*)(g_cur + (size_t)c0 * DD + c * 4);
        float4 x1 = *(const float4*)(g_cur + (size_t)c1 * DD + c * 4);
        acc.x += p0.y * x0.x + p1.y * x1.x;
        acc.y += p0.y * x0.y + p1.y * x1.y;
        acc.z += p0.y * x0.z + p1.y * x1.z;
        acc.w += p0.y * x0.w + p1.y * x1.w;
    }
    if (i < e) {
        float2 p0 = __ldg(&g_epayG[i]);
        int c0 = __float_as_int(p0.x);
        float4 x0 = *(const float4*)(g_cur + (size_t)c0 * DD + c * 4);
        acc.x += p0.y * x0.x; acc.y += p0.y * x0.y;
        acc.z += p0.y * x0.z; acc.w += p0.y * x0.w;
    }
    *(float4*)(g_gnn + (size_t)r * DD + c * 4) = acc;
}

// ---------------- DCCF: intent via wmma bf16 double-split ----------------
// 128 rows/block, 256 threads (8 warps, 16 rows each).
// smem bytes:
//   WH 0..16384, WL 16384..32768          (64x128 bf16 hi/lo)
//   UH 32768..49152, UL 49152..65536      (128x64 bf16 hi/lo)
//   S  65536..133120                      (128x132 f32 scores / 128x68 out stage)
//   PH 133120..165888, PL 165888..198656  (128x128 bf16 hi/lo)
#define ITW_SMEM 198656

__global__ void __launch_bounds__(256) k_intent_wmma(const float* __restrict__ Wu,
                                                     const float* __restrict__ Wi) {
    extern __shared__ char smb[];
    __nv_bfloat16* WH = (__nv_bfloat16*)(smb);
    __nv_bfloat16* WL = (__nv_bfloat16*)(smb + 16384);
    __nv_bfloat16* UH = (__nv_bfloat16*)(smb + 32768);
    __nv_bfloat16* UL = (__nv_bfloat16*)(smb + 49152);
    float*         S  = (float*)(smb + 65536);
    __nv_bfloat16* PH = (__nv_bfloat16*)(smb + 133120);
    __nv_bfloat16* PL = (__nv_bfloat16*)(smb + 165888);

    const int tid = threadIdx.x, w = tid >> 5;
    const int UBt = (NU + 127) / 128;  // 782
    const bool isUser = (int)blockIdx.x < UBt;
    const float* Wg = isUser ? Wu : Wi;
    const int rowbase = isUser ? (int)blockIdx.x * 128 : NU + ((int)blockIdx.x - UBt) * 128;
    const int rowlim = isUser ? NU : NN;

    // stage W (64x128) hi/lo
    for (int t = tid; t < 8192; t += 256) {
        float x = Wg[t];
        __nv_bfloat16 h = __float2bfloat16(x);
        __nv_bfloat16 l = __float2bfloat16(x - __bfloat162float(h));
        WH[t] = h; WL[t] = l;
    }
    // stage u (128x64) hi/lo
    for (int t = tid; t < 8192; t += 256) {
        int r = t >> 6, k = t & 63;
        int gr = rowbase + r;
        float x = (gr < rowlim) ? g_cur[(size_t)gr * DD + k] : 0.f;
        __nv_bfloat16 h = __float2bfloat16(x);
        __nv_bfloat16 l = __float2bfloat16(x - __bfloat162float(h));
        UH[t] = h; UL[t] = l;
    }
    __syncthreads();

    // ---- pass 1: S = u @ W ----
    {
        wmma::fragment<wmma::matrix_a, 16, 16, 16, __nv_bfloat16, wmma::row_major> aH[4], aL[4];
#pragma unroll
        for (int k = 0; k < 4; k++) {
            wmma::load_matrix_sync(aH[k], UH + (16 * w) * 64 + 16 * k, 64);
            wmma::load_matrix_sync(aL[k], UL + (16 * w) * 64 + 16 * k, 64);
        }
#pragma unroll
        for (int n = 0; n < 8; n++) {
            wmma::fragment<wmma::accumulator, 16, 16, 16, float> acc;
            wmma::fill_fragment(acc, 0.f);
#pragma unroll
            for (int k = 0; k < 4; k++) {
                wmma::fragment<wmma::matrix_b, 16, 16, 16, __nv_bfloat16, wmma::row_major> bH, bL;
                wmma::load_matrix_sync(bH, WH + (16 * k) * 128 + 16 * n, 128);
                wmma::load_matrix_sync(bL, WL + (16 * k) * 128 + 16 * n, 128);
                wmma::mma_sync(acc, aH[k], bH, acc);
                wmma::mma_sync(acc, aL[k], bH, acc);
                wmma::mma_sync(acc, aH[k], bL, acc);
            }
            wmma::store_matrix_sync(S + (16 * w) * 132 + 16 * n, acc, 132, wmma::mem_row_major);
        }
    }
    __syncthreads();

    // ---- softmax: 2 threads per row ----
    {
        const int r = tid >> 1, half = tid & 1;
        float v[64];
        float mx = -3.4e38f;
#pragma unroll
        for (int c = 0; c < 64; c++) {
            v[c] = S[r * 132 + half * 64 + c];
            mx = fmaxf(mx, v[c]);
        }
        mx = fmaxf(mx, __shfl_xor_sync(0xffffffffu, mx, 1));
        float sum = 0.f;
#pragma unroll
        for (int c = 0; c < 64; c++) {
            v[c] = __expf(v[c] - mx);
            sum += v[c];
        }
        sum += __shfl_xor_sync(0xffffffffu, sum, 1);
        float inv = 1.f / sum;
#pragma unroll
        for (int c = 0; c < 64; c++) {
            float p = v[c] * inv;
            __nv_bfloat16 h = __float2bfloat16(p);
            __nv_bfloat16 l = __float2bfloat16(p - __bfloat162float(h));
            PH[r * 128 + half * 64 + c] = h;
            PL[r * 128 + half * 64 + c] = l;
        }
    }
    __syncthreads();

    // ---- pass 2: out = p @ W^T (W smem reused via col_major B fragments) ----
    {
        wmma::fragment<wmma::matrix_a, 16, 16, 16, __nv_bfloat16, wmma::row_major> pHf[8], pLf[8];
#pragma unroll
        for (int k = 0; k < 8; k++) {
            wmma::load_matrix_sync(pHf[k], PH + (16 * w) * 128 + 16 * k, 128);
            wmma::load_matrix_sync(pLf[k], PL + (16 * w) * 128 + 16 * k, 128);
        }
#pragma unroll
        for (int n = 0; n < 4; n++) {
            wmma::fragment<wmma::accumulator, 16, 16, 16, float> acc;
            wmma::fill_fragment(acc, 0.f);
#pragma unroll
            for (int k = 0; k < 8; k++) {
                wmma::fragment<wmma::matrix_b, 16, 16, 16, __nv_bfloat16, wmma::col_major> bH, bL;
                wmma::load_matrix_sync(bH, WH + (16 * n) * 128 + 16 * k, 128);
                wmma::load_matrix_sync(bL, WL + (16 * n) * 128 + 16 * k, 128);
                wmma::mma_sync(acc, pHf[k], bH, acc);
                wmma::mma_sync(acc, pLf[k], bH, acc);
                wmma::mma_sync(acc, pHf[k], bL, acc);
            }
            wmma::store_matrix_sync(S + (16 * w) * 68 + 16 * n, acc, 68, wmma::mem_row_major);
        }
    }
    __syncthreads();

    // ---- epilogue: residual + total ----
    {
        const int r = tid >> 1, half = tid & 1;
        int gr = rowbase + r;
        if (gr < rowlim) {
            size_t base = (size_t)gr * DD + half * 32;
            const float* srow = S + r * 68 + half * 32;
#pragma unroll
            for (int q = 0; q < 8; q++) {
                float4 ov = *(const float4*)(srow + q * 4);
                float4 gn = *(const float4*)(g_gnn + base + q * 4);
                float4 cu = *(const float4*)(g_cur + base + q * 4);
                float4 tt = *(const float4*)(g_total + base + q * 4);
                float4 nv;
                nv.x = gn.x + ov.x + cu.x;
                nv.y = gn.y + ov.y + cu.y;
                nv.z = gn.z + ov.z + cu.z;
                nv.w = gn.w + ov.w + cu.w;
                *(float4*)(g_cur + base + q * 4) = nv;
                tt.x += nv.x; tt.y += nv.y; tt.z += nv.z; tt.w += nv.w;
                *(float4*)(g_total + base + q * 4) = tt;
            }
        }
    }
}

// ---------------- HAN: CSR gather ----------------
__global__ void __launch_bounds__(256) k_hgather(const float* __restrict__ feat, int E2,
                                                 int n, int base, int rbase, int paybase,
                                                 int zbase) {
    unsigned t = blockIdx.x * 256u + threadIdx.x;
    unsigned idx = t >> 4;
    unsigned c = t & 15u;
    if (idx >= 2u * (unsigned)n) return;
    int m = (idx >= (unsigned)n) ? 1 : 0;
    int node = (int)idx - m * n;
    const int* rptr = g_rptrH + rbase + m * (n + 1);
    int s = rptr[node], e = rptr[node + 1];
    const int* pay = g_hpay + paybase + m * E2;
    const int* dout = g_dout + base + m * n;
    float4 acc = make_float4(0.f, 0.f, 0.f, 0.f);
    int i = s;
    for (; i + 2 <= e; i += 2) {
        int s0 = __ldg(pay + i), s1 = __ldg(pay + i + 1);
        float w0 = rsqrtf((float)__ldg(dout + s0));
        float w1 = rsqrtf((float)__ldg(dout + s1));
        float4 x0 = *(const float4*)(feat + (size_t)s0 * DD + c * 4);
        float4 x1 = *(const float4*)(feat + (size_t)s1 * DD + c * 4);
        acc.x += w0 * x0.x + w1 * x1.x;
        acc.y += w0 * x0.y + w1 * x1.y;
        acc.z += w0 * x0.z + w1 * x1.z;
        acc.w += w0 * x0.w + w1 * x1.w;
    }
    if (i < e) {
        int s0 = __ldg(pay + i);
        float w0 = rsqrtf((float)__ldg(dout + s0));
        float4 x0 = *(const float4*)(feat + (size_t)s0 * DD + c * 4);
        acc.x += w0 * x0.x; acc.y += w0 * x0.y;
        acc.z += w0 * x0.z; acc.w += w0 * x0.w;
    }
    float din = (float)(e - s);
    float sc = (din > 0.f) ? rsqrtf(din) : 0.f;
    *(float4*)(g_z + (size_t)zbase + ((size_t)node * 2 + m) * DD + c * 4) =
        make_float4(acc.x * sc, acc.y * sc, acc.z * sc, acc.w * sc);
}

// ---------------- HAN: semantic attention logits ----------------
__global__ void __launch_bounds__(256) k_han_node(const float* __restrict__ W1g,
                                                  const float* __restrict__ b1g,
                                                  const float* __restrict__ w2g,
                                                  int n, int zbase, int wbase) {
    __shared__ float Wsm[8192];
    __shared__ float ush[4096];
    __shared__ float bsh[128];
    __shared__ float w2sh[128];
    __shared__ float wacc[2];

    const int tid = threadIdx.x, w = tid >> 5, lane = tid & 31;
    for (int t = tid; t < 2048; t += 256) {
        int k = t >> 5, L = t & 31;
        ((float4*)Wsm)[t] = *(const float4*)(W1g + k * 128 + L * 4);
    }
    if (tid < 128) { bsh[tid] = b1g[tid]; w2sh[tid] = w2g[tid]; }
    if (tid < 2) wacc[tid] = 0.f;
    __syncthreads();

    const int rows = 2 * n;
    const int r0 = (int)blockIdx.x * 64 + w * 8;
    float* u = ush + w * 512;

    for (int t = lane; t < 512; t += 32) {
        int rr = t >> 6, d = t & 63;
        int row = r0 + rr;
        u[t] = (row < rows) ? g_z[(size_t)zbase + (size_t)row * DD + d] : 0.f;
    }
    __syncwarp();

    float acc[8][4];
#pragma unroll
    for (int a = 0; a < 8; a++) { acc[a][0] = acc[a][1] = acc[a][2] = acc[a][3] = 0.f; }

#pragma unroll 2
    for (int kk = 0; kk < 16; kk++) {
        float4 w0 = ((const float4*)Wsm)[(4 * kk + 0) * 32 + lane];
        float4 w1 = ((const float4*)Wsm)[(4 * kk + 1) * 32 + lane];
        float4 w2 = ((const float4*)Wsm)[(4 * kk + 2) * 32 + lane];
        float4 w3 = ((const float4*)Wsm)[(4 * kk + 3) * 32 + lane];
#pragma unroll
        for (int rr = 0; rr < 8; rr++) {
            float4 uv = *(const float4*)(u + rr * 64 + kk * 4);
            acc[rr][0] += uv.x * w0.x + uv.y * w1.x + uv.z * w2.x + uv.w * w3.x;
            acc[rr][1] += uv.x * w0.y + uv.y * w1.y + uv.z * w2.y + uv.w * w3.y;
            acc[rr][2] += uv.x * w0.z + uv.y * w1.z + uv.z * w2.z + uv.w * w3.z;
            acc[rr][3] += uv.x * w0.w + uv.y * w1.w + uv.z * w2.w + uv.w * w3.w;
        }
    }

    float wl01[2] = {0.f, 0.f};
#pragma unroll
    for (int rr = 0; rr < 8; rr++) {
        int row = r0 + rr;
        float wl = 0.f;
#pragma unroll
        for (int c = 0; c < 4; c++) {
            int j = lane * 4 + c;
            wl += tanhf(acc[rr][c] + bsh[j]) * w2sh[j];
        }
        if (row < rows) wl01[row & 1] += wl;
    }
#pragma unroll
    for (int off = 16; off; off >>= 1) {
        wl01[0] += __shfl_xor_sync(0xffffffffu, wl01[0], off);
        wl01[1] += __shfl_xor_sync(0xffffffffu, wl01[1], off);
    }
    if (lane == 0) {
        atomicAdd(&wacc[0], wl01[0]);
        atomicAdd(&wacc[1], wl01[1]);
    }
    __syncthreads();
    if (tid < 2) atomicAdd(&g_wsum[wbase + tid], wacc[tid]);
}

// ---------------- final combine ----------------
__global__ void __launch_bounds__(256) k_combine(float* __restrict__ out) {
    unsigned i = blockIdx.x * 256u + threadIdx.x;
    if (i >= (unsigned)(NN * DD)) return;
    unsigned node = i >> 6, d = i & 63u;
    float w0, w1;
    size_t zr;
    if (node < NU) {
        w0 = g_wsum[0] * (1.f / NU);
        w1 = g_wsum[1] * (1.f / NU);
        zr = (size_t)node * 128;
    } else {
        w0 = g_wsum[2] * (1.f / NI);
        w1 = g_wsum[3] * (1.f / NI);
        zr = (size_t)NU * 128 + (size_t)(node - NU) * 128;
    }
    float mx = fmaxf(w0, w1);
    float e0 = __expf(w0 - mx), e1 = __expf(w1 - mx);
    float inv = 1.f / (e0 + e1);
    float han = (e0 * inv) * g_z[zr + d] + (e1 * inv) * g_z[zr + 64 + d];
    out[i] = 0.5f * g_total[i] + 0.5f * han;
}

// ---------------- launcher ----------------
extern "C" void kernel_launch(void* const* d_in, const int* in_sizes, int n_in,
                              void* d_out, int out_size) {
    const int*   G    = (const int*)d_in[0];
    const float* Gv   = (const float*)d_in[1];
    const float* fu   = (const float*)d_in[2];
    const float* fi   = (const float*)d_in[3];
    const float* Wu   = (const float*)d_in[4];
    const float* Wi   = (const float*)d_in[5];
    const int*   eu   = (const int*)d_in[6];
    const int*   ei   = (const int*)d_in[7];
    const float* suW1 = (const float*)d_in[8];
    const float* sub1 = (const float*)d_in[9];
    const float* suw2 = (const float*)d_in[10];
    const float* siW1 = (const float*)d_in[11];
    const float* sib1 = (const float*)d_in[12];
    const float* siw2 = (const float*)d_in[13];
    float* out = (float*)d_out;

    cudaFuncSetAttribute(k_intent_wmma, cudaFuncAttributeMaxDynamicSharedMemorySize, ITW_SMEM);

    const int UBt = (NU + 127) / 128;   // 782
    const int IBt = (NI + 127) / 128;   // 391

    // init + CSR build
    k_zero_cnt<<<1172, 256>>>();
    k_init<<<37500, 256>>>(fu, fi);
    k_histG<<<12500, 256>>>(G);
    k_histH<<<12500, 256>>>(eu, EU_, NU, 0);
    k_histH<<<6250, 256>>>(ei, EI_, NI, 2 * NU);
    k_scan<<<5, 1024>>>();
    k_fillG<<<12500, 256>>>(G, Gv);
    k_fillH<<<12500, 256>>>(eu, EU_, NU, 0, 0, 0);
    k_fillH<<<6250, 256>>>(ei, EI_, NI, 2 * NU, 2 * (NU + 1), 2 * EU_);

    // DCCF layers
    for (int layer = 0; layer < 2; layer++) {
        k_spmm_csr<<<9375, 256>>>();
        k_intent_wmma<<<UBt + IBt, 256, ITW_SMEM>>>(Wu, Wi);
    }

    // HAN
    k_hgather<<<12500, 256>>>(fu, EU_, NU, 0, 0, 0, 0);
    k_hgather<<<6250, 256>>>(fi, EI_, NI, 2 * NU, 2 * (NU + 1), 2 * EU_, NU * 128);
    k_han_node<<<3125, 256>>>(suW1, sub1, suw2, NU, 0, 0);
    k_han_node<<<1563, 256>>>(siW1, sib1, siw2, NI, NU * 128, 2);
    k_combine<<<37500, 256>>>(out);
}

// round 8
// speedup vs baseline: 1.2955x; 1.2955x over previous
#include <cuda_runtime.h>

#define NU 100000
#define NI 50000
#define NN 150000
#define DD 64
#define EG 3200000
#define EU_ 1600000
#define EI_ 800000

typedef unsigned long long ull;

// ---------------- device scratch ----------------
__device__ float g_cur[NN * DD];
__device__ float g_gnn[NN * DD];
__device__ float g_total[NN * DD];
__device__ float g_z[NN * 2 * DD];        // row = node*2 + metapath
__device__ float g_wsum[4];

// CSR for G
__device__ int    g_cntG[NN];
__device__ int    g_curG[NN];
__device__ int    g_rptrG[NN + 1];
__device__ float2 g_epayG[EG];            // {col_bits, val}

// CSR + degrees for HAN (4 graphs: u-mp0, u-mp1, i-mp0, i-mp1)
#define HN (2 * NU + 2 * NI)
__device__ int g_dout[HN];
__device__ int g_din[HN];
__device__ int g_curH[HN];
__device__ int g_rptrH[2 * (NU + 1) + 2 * (NI + 1)];
__device__ int g_hpay[2 * EU_ + 2 * EI_];

// f32x2 packed math (sm_100+)
__device__ __forceinline__ ull pk2(float a) {
    ull r;
    asm("mov.b64 %0, {%1, %1};" : "=l"(r) : "f"(a));
    return r;
}
__device__ __forceinline__ ull pack2(float lo, float hi) {
    ull r;
    asm("mov.b64 %0, {%1, %2};" : "=l"(r) : "f"(lo), "f"(hi));
    return r;
}
__device__ __forceinline__ void fma2(ull& d, ull a, ull b) {
    asm("fma.rn.f32x2 %0, %1, %2, %0;" : "+l"(d) : "l"(a), "l"(b));
}
__device__ __forceinline__ float2 up2(ull v) {
    float2 f;
    asm("mov.b64 {%0, %1}, %2;" : "=f"(f.x), "=f"(f.y) : "l"(v));
    return f;
}

// ---------------- zero counters ----------------
__global__ void __launch_bounds__(256) k_zero_cnt() {
    unsigned i = blockIdx.x * 256u + threadIdx.x;
    if (i < NN) { g_cntG[i] = 0; g_curG[i] = 0; }
    if (i < HN) { g_dout[i] = 0; g_din[i] = 0; g_curH[i] = 0; }
    if (i < 4u) g_wsum[i] = 0.f;
}

// ---------------- init ----------------
__global__ void __launch_bounds__(256) k_init(const float* __restrict__ fu,
                                              const float* __restrict__ fi) {
    unsigned i = blockIdx.x * 256u + threadIdx.x;
    if (i < NU * DD) {
        float v = fu[i];
        g_cur[i] = v; g_total[i] = v;
    } else if (i < NN * DD) {
        float v = fi[i - NU * DD];
        g_cur[i] = v; g_total[i] = v;
    }
}

// ---------------- CSR build ----------------
__global__ void __launch_bounds__(256) k_histG(const int* __restrict__ G) {
    unsigned e = blockIdx.x * 256u + threadIdx.x;
    if (e >= EG) return;
    atomicAdd(&g_cntG[__ldg(G + e)], 1);
}

__global__ void __launch_bounds__(256) k_histH(const int* __restrict__ edges, int E2,
                                               int n, int base) {
    unsigned t = blockIdx.x * 256u + threadIdx.x;
    if (t >= 2u * (unsigned)E2) return;
    int m = (t >= (unsigned)E2) ? 1 : 0;
    int e = (int)t - m * E2;
    int src = __ldg(edges + (size_t)m * 2 * E2 + e);
    int dst = __ldg(edges + (size_t)m * 2 * E2 + E2 + e);
    atomicAdd(&g_dout[base + m * n + src], 1);
    atomicAdd(&g_din[base + m * n + dst], 1);
}

__global__ void __launch_bounds__(1024) k_scan() {
    const int* cnt; int* rptr; int n;
    switch (blockIdx.x) {
        case 0: cnt = g_cntG;              rptr = g_rptrG;                          n = NN; break;
        case 1: cnt = g_din;               rptr = g_rptrH;                          n = NU; break;
        case 2: cnt = g_din + NU;          rptr = g_rptrH + (NU + 1);               n = NU; break;
        case 3: cnt = g_din + 2 * NU;      rptr = g_rptrH + 2 * (NU + 1);           n = NI; break;
        default: cnt = g_din + 2 * NU + NI; rptr = g_rptrH + 2 * (NU + 1) + (NI + 1); n = NI; break;
    }
    __shared__ int wsum[32];
    __shared__ int s_carry;
    const int tid = threadIdx.x, lane = tid & 31, wid = tid >> 5;
    if (tid == 0) s_carry = 0;
    __syncthreads();
    for (int base = 0; base < n; base += 1024) {
        int i = base + tid;
        int v = (i < n) ? cnt[i] : 0;
        int x = v;
#pragma unroll
        for (int off = 1; off < 32; off <<= 1) {
            int y = __shfl_up_sync(0xffffffffu, x, off);
            if (lane >= off) x += y;
        }
        if (lane == 31) wsum[wid] = x;
        __syncthreads();
        if (wid == 0) {
            int s = wsum[lane];
#pragma unroll
            for (int off = 1; off < 32; off <<= 1) {
                int y = __shfl_up_sync(0xffffffffu, s, off);
                if (lane >= off) s += y;
            }
            wsum[lane] = s;
        }
        __syncthreads();
        int excl = x - v + (wid > 0 ? wsum[wid - 1] : 0) + s_carry;
        int ctot = wsum[31];
        if (i < n) rptr[i] = excl;
        __syncthreads();
        if (tid == 0) s_carry += ctot;
        __syncthreads();
    }
    if (tid == 0) rptr[n] = s_carry;
}

__global__ void __launch_bounds__(256) k_fillG(const int* __restrict__ G,
                                               const float* __restrict__ gv) {
    unsigned e = blockIdx.x * 256u + threadIdx.x;
    if (e >= EG) return;
    int row = __ldg(G + e);
    int col = __ldg(G + EG + e);
    float v = __ldg(gv + e);
    int pos = g_rptrG[row] + atomicAdd(&g_curG[row], 1);
    g_epayG[pos] = make_float2(__int_as_float(col), v);
}

__global__ void __launch_bounds__(256) k_fillH(const int* __restrict__ edges, int E2,
                                               int n, int base, int rbase, int paybase) {
    unsigned t = blockIdx.x * 256u + threadIdx.x;
    if (t >= 2u * (unsigned)E2) return;
    int m = (t >= (unsigned)E2) ? 1 : 0;
    int e = (int)t - m * E2;
    int src = __ldg(edges + (size_t)m * 2 * E2 + e);
    int dst = __ldg(edges + (size_t)m * 2 * E2 + E2 + e);
    const int* rptr = g_rptrH + rbase + m * (n + 1);
    int pos = rptr[dst] + atomicAdd(&g_curH[base + m * n + dst], 1);
    g_hpay[paybase + m * E2 + pos] = src;
}

// ---------------- DCCF: CSR SpMM ----------------
__global__ void __launch_bounds__(256) k_spmm_csr() {
    unsigned t = blockIdx.x * 256u + threadIdx.x;
    unsigned r = t >> 4;
    unsigned c = t & 15u;
    if (r >= NN) return;
    int s = g_rptrG[r], e = g_rptrG[r + 1];
    float4 acc = make_float4(0.f, 0.f, 0.f, 0.f);
    int i = s;
    for (; i + 2 <= e; i += 2) {
        float2 p0 = __ldg(&g_epayG[i]);
        float2 p1 = __ldg(&g_epayG[i + 1]);
        int c0 = __float_as_int(p0.x), c1 = __float_as_int(p1.x);
        float4 x0 = *(const float4*)(g_cur + (size_t)c0 * DD + c * 4);
        float4 x1 = *(const float4*)(g_cur + (size_t)c1 * DD + c * 4);
        acc.x += p0.y * x0.x + p1.y * x1.x;
        acc.y += p0.y * x0.y + p1.y * x1.y;
        acc.z += p0.y * x0.z + p1.y * x1.z;
        acc.w += p0.y * x0.w + p1.y * x1.w;
    }
    if (i < e) {
        float2 p0 = __ldg(&g_epayG[i]);
        int c0 = __float_as_int(p0.x);
        float4 x0 = *(const float4*)(g_cur + (size_t)c0 * DD + c * 4);
        acc.x += p0.y * x0.x; acc.y += p0.y * x0.y;
        acc.z += p0.y * x0.z; acc.w += p0.y * x0.w;
    }
    *(float4*)(g_gnn + (size_t)r * DD + c * 4) = acc;
}

// ---------------- DCCF: intent — f32x2 row-pair, single W layout, 2 CTA/SM ----------------
// smem (floats):
//   WTp [0 .. 8448)       {W[2L][j], W[2L+1][j]} float2 at j*33+L   (33792 B)
//   uT2 [8448 .. 12544)   8 warps * 256 u64 {u[2p][k],u[2p+1][k]} at p*64+k (16384 B)
//   pT2 [12544 .. 20736)  8 warps * 512 u64 {p[2p][j],p[2p+1][j]} at p*128+j (32768 B)
// total 20736 floats = 82944 B -> 2 CTAs/SM
#define INTENT_SMEM 82944
#define IT_THREADS 256
#define IT_ROWS_PER_BLOCK 64

__global__ void __launch_bounds__(IT_THREADS) k_intent(const float* __restrict__ Wu,
                                                       const float* __restrict__ Wi) {
    extern __shared__ float sm[];
    float2* WTpw = (float2*)sm;
    const float2* WTp = (const float2*)sm;
    const int tid = threadIdx.x, w = tid >> 5, lane = tid & 31;

    ull* uT2 = (ull*)(sm + 8448) + w * 256;
    ull* pT2 = (ull*)(sm + 12544) + w * 512;

    const int UB = (NU + IT_ROWS_PER_BLOCK - 1) / IT_ROWS_PER_BLOCK;  // 1563
    const bool isUser = (int)blockIdx.x < UB;
    const float* Wg = isUser ? Wu : Wi;
    const int rowbase = isUser ? (int)blockIdx.x * IT_ROWS_PER_BLOCK
                               : NU + ((int)blockIdx.x - UB) * IT_ROWS_PER_BLOCK;
    const int rowlim = isUser ? NU : NN;

    // stage WTp directly from global (coalesced: consecutive t -> consecutive j)
    for (int t = tid; t < 4096; t += IT_THREADS) {
        int L = t >> 7, j = t & 127;
        WTpw[j * 33 + L] = make_float2(Wg[(2 * L) * 128 + j], Wg[(2 * L + 1) * 128 + j]);
    }
    __syncthreads();

    const int r0 = rowbase + w * 8;

    // load u transposed + row-paired
    for (int t = lane; t < 256; t += 32) {
        int rho = t >> 6, k = t & 63;
        int ra = r0 + 2 * rho, rb = ra + 1;
        float xa = (ra < rowlim) ? g_cur[(size_t)ra * DD + k] : 0.f;
        float xb = (rb < rowlim) ? g_cur[(size_t)rb * DD + k] : 0.f;
        uT2[rho * 64 + k] = pack2(xa, xb);
    }
    __syncwarp();

    // ---- pass 1: scores = u @ W.  acc[rho][jj]: rows (2rho,2rho+1) packed, j = lane + 32*jj
    ull acc[4][4];
#pragma unroll
    for (int a = 0; a < 4; a++) { acc[a][0] = acc[a][1] = acc[a][2] = acc[a][3] = 0ull; }

    const ulonglong2* uT2v = (const ulonglong2*)uT2;
#pragma unroll 4
    for (int L = 0; L < 32; L++) {
        float2 w0 = WTp[(lane +  0) * 33 + L];
        float2 w1 = WTp[(lane + 32) * 33 + L];
        float2 w2 = WTp[(lane + 64) * 33 + L];
        float2 w3 = WTp[(lane + 96) * 33 + L];
        ull s0x = pk2(w0.x), s0y = pk2(w0.y);
        ull s1x = pk2(w1.x), s1y = pk2(w1.y);
        ull s2x = pk2(w2.x), s2y = pk2(w2.y);
        ull s3x = pk2(w3.x), s3y = pk2(w3.y);
#pragma unroll
        for (int rho = 0; rho < 4; rho++) {
            ulonglong2 up = uT2v[rho * 32 + L];   // {u-pair k=2L, u-pair k=2L+1}
            fma2(acc[rho][0], s0x, up.x); fma2(acc[rho][0], s0y, up.y);
            fma2(acc[rho][1], s1x, up.x); fma2(acc[rho][1], s1y, up.y);
            fma2(acc[rho][2], s2x, up.x); fma2(acc[rho][2], s2y, up.y);
            fma2(acc[rho][3], s3x, up.x); fma2(acc[rho][3], s3y, up.y);
        }
    }

    // ---- softmax per row (both parities); lane owns j = lane + 32*jj ----
#pragma unroll
    for (int rho = 0; rho < 4; rho++) {
        float2 a0 = up2(acc[rho][0]), a1 = up2(acc[rho][1]);
        float2 a2 = up2(acc[rho][2]), a3 = up2(acc[rho][3]);
        float ml = fmaxf(fmaxf(a0.x, a1.x), fmaxf(a2.x, a3.x));
        float mh = fmaxf(fmaxf(a0.y, a1.y), fmaxf(a2.y, a3.y));
#pragma unroll
        for (int off = 16; off; off >>= 1) {
            ml = fmaxf(ml, __shfl_xor_sync(0xffffffffu, ml, off));
            mh = fmaxf(mh, __shfl_xor_sync(0xffffffffu, mh, off));
        }
        float el0 = __expf(a0.x - ml), el1 = __expf(a1.x - ml);
        float el2 = __expf(a2.x - ml), el3 = __expf(a3.x - ml);
        float eh0 = __expf(a0.y - mh), eh1 = __expf(a1.y - mh);
        float eh2 = __expf(a2.y - mh), eh3 = __expf(a3.y - mh);
        float sl = el0 + el1 + el2 + el3;
        float sh = eh0 + eh1 + eh2 + eh3;
#pragma unroll
        for (int off = 16; off; off >>= 1) {
            sl += __shfl_xor_sync(0xffffffffu, sl, off);
            sh += __shfl_xor_sync(0xffffffffu, sh, off);
        }
        float il = 1.f / sl, ih = 1.f / sh;
        pT2[rho * 128 + lane +  0] = pack2(el0 * il, eh0 * ih);
        pT2[rho * 128 + lane + 32] = pack2(el1 * il, eh1 * ih);
        pT2[rho * 128 + lane + 64] = pack2(el2 * il, eh2 * ih);
        pT2[rho * 128 + lane + 96] = pack2(el3 * il, eh3 * ih);
    }
    __syncwarp();

    // ---- pass 2: out = p @ W^T.  acc2[rho][dc]: rows packed, dims d = 2*lane+dc
    ull acc2[4][2];
#pragma unroll
    for (int a = 0; a < 4; a++) { acc2[a][0] = 0ull; acc2[a][1] = 0ull; }

    const ulonglong2* pT2v = (const ulonglong2*)pT2;
#pragma unroll 2
    for (int j4 = 0; j4 < 32; j4++) {
        ulonglong2 P0a = pT2v[0 * 64 + 2 * j4], P0b = pT2v[0 * 64 + 2 * j4 + 1];
        ulonglong2 P1a = pT2v[1 * 64 + 2 * j4], P1b = pT2v[1 * 64 + 2 * j4 + 1];
        ulonglong2 P2a = pT2v[2 * 64 + 2 * j4], P2b = pT2v[2 * 64 + 2 * j4 + 1];
        ulonglong2 P3a = pT2v[3 * 64 + 2 * j4], P3b = pT2v[3 * 64 + 2 * j4 + 1];
#define P2J(JJ, PW)                                             \
        {                                                       \
            float2 wt = WTp[(4 * j4 + JJ) * 33 + lane];         \
            ull s0 = pk2(wt.x), s1 = pk2(wt.y);                 \
            fma2(acc2[0][0], s0, P0##PW); fma2(acc2[0][1], s1, P0##PW); \
            fma2(acc2[1][0], s0, P1##PW); fma2(acc2[1][1], s1, P1##PW); \
            fma2(acc2[2][0], s0, P2##PW); fma2(acc2[2][1], s1, P2##PW); \
            fma2(acc2[3][0], s0, P3##PW); fma2(acc2[3][1], s1, P3##PW); \
        }
        P2J(0, a.x) P2J(1, a.y) P2J(2, b.x) P2J(3, b.y)
#undef P2J
    }

    // ---- epilogue: residual + total ----
#pragma unroll
    for (int rho = 0; rho < 4; rho++) {
        float2 o0 = up2(acc2[rho][0]);
        float2 o1 = up2(acc2[rho][1]);
#pragma unroll
        for (int par = 0; par < 2; par++) {
            int r = r0 + 2 * rho + par;
            if (r >= rowlim) continue;
            float oa = par ? o0.y : o0.x;
            float ob = par ? o1.y : o1.x;
            size_t base = (size_t)r * DD + lane * 2;
            float2 cu = *(const float2*)(g_cur + base);
            float2 gn = *(const float2*)(g_gnn + base);
            float2 tt = *(const float2*)(g_total + base);
            float n0 = gn.x + oa + cu.x;
            float n1 = gn.y + ob + cu.y;
            *(float2*)(g_cur + base) = make_float2(n0, n1);
            *(float2*)(g_total + base) = make_float2(tt.x + n0, tt.y + n1);
        }
    }
}

// ---------------- HAN: CSR gather ----------------
__global__ void __launch_bounds__(256) k_hgather(const float* __restrict__ feat, int E2,
                                                 int n, int base, int rbase, int paybase,
                                                 int zbase) {
    unsigned t = blockIdx.x * 256u + threadIdx.x;
    unsigned idx = t >> 4;
    unsigned c = t & 15u;
    if (idx >= 2u * (unsigned)n) return;
    int m = (idx >= (unsigned)n) ? 1 : 0;
    int node = (int)idx - m * n;
    const int* rptr = g_rptrH + rbase + m * (n + 1);
    int s = rptr[node], e = rptr[node + 1];
    const int* pay = g_hpay + paybase + m * E2;
    const int* dout = g_dout + base + m * n;
    float4 acc = make_float4(0.f, 0.f, 0.f, 0.f);
    int i = s;
    for (; i + 2 <= e; i += 2) {
        int s0 = __ldg(pay + i), s1 = __ldg(pay + i + 1);
        float w0 = rsqrtf((float)__ldg(dout + s0));
        float w1 = rsqrtf((float)__ldg(dout + s1));
        float4 x0 = *(const float4*)(feat + (size_t)s0 * DD + c * 4);
        float4 x1 = *(const float4*)(feat + (size_t)s1 * DD + c * 4);
        acc.x += w0 * x0.x + w1 * x1.x;
        acc.y += w0 * x0.y + w1 * x1.y;
        acc.z += w0 * x0.z + w1 * x1.z;
        acc.w += w0 * x0.w + w1 * x1.w;
    }
    if (i < e) {
        int s0 = __ldg(pay + i);
        float w0 = rsqrtf((float)__ldg(dout + s0));
        float4 x0 = *(const float4*)(feat + (size_t)s0 * DD + c * 4);
        acc.x += w0 * x0.x; acc.y += w0 * x0.y;
        acc.z += w0 * x0.z; acc.w += w0 * x0.w;
    }
    float din = (float)(e - s);
    float sc = (din > 0.f) ? rsqrtf(din) : 0.f;
    *(float4*)(g_z + (size_t)zbase + ((size_t)node * 2 + m) * DD + c * 4) =
        make_float4(acc.x * sc, acc.y * sc, acc.z * sc, acc.w * sc);
}

// ---------------- HAN: semantic attention logits ----------------
__global__ void __launch_bounds__(256) k_han_node(const float* __restrict__ W1g,
                                                  const float* __restrict__ b1g,
                                                  const float* __restrict__ w2g,
                                                  int n, int zbase, int wbase) {
    __shared__ float Wsm[8192];
    __shared__ float ush[4096];
    __shared__ float bsh[128];
    __shared__ float w2sh[128];
    __shared__ float wacc[2];

    const int tid = threadIdx.x, w = tid >> 5, lane = tid & 31;
    for (int t = tid; t < 2048; t += 256) {
        int k = t >> 5, L = t & 31;
        ((float4*)Wsm)[t] = *(const float4*)(W1g + k * 128 + L * 4);
    }
    if (tid < 128) { bsh[tid] = b1g[tid]; w2sh[tid] = w2g[tid]; }
    if (tid < 2) wacc[tid] = 0.f;
    __syncthreads();

    const int rows = 2 * n;
    const int r0 = (int)blockIdx.x * 64 + w * 8;
    float* u = ush + w * 512;

    for (int t = lane; t < 512; t += 32) {
        int rr = t >> 6, d = t & 63;
        int row = r0 + rr;
        u[t] = (row < rows) ? g_z[(size_t)zbase + (size_t)row * DD + d] : 0.f;
    }
    __syncwarp();

    float acc[8][4];
#pragma unroll
    for (int a = 0; a < 8; a++) { acc[a][0] = acc[a][1] = acc[a][2] = acc[a][3] = 0.f; }

#pragma unroll 2
    for (int kk = 0; kk < 16; kk++) {
        float4 w0 = ((const float4*)Wsm)[(4 * kk + 0) * 32 + lane];
        float4 w1 = ((const float4*)Wsm)[(4 * kk + 1) * 32 + lane];
        float4 w2 = ((const float4*)Wsm)[(4 * kk + 2) * 32 + lane];
        float4 w3 = ((const float4*)Wsm)[(4 * kk + 3) * 32 + lane];
#pragma unroll
        for (int rr = 0; rr < 8; rr++) {
            float4 uv = *(const float4*)(u + rr * 64 + kk * 4);
            acc[rr][0] += uv.x * w0.x + uv.y * w1.x + uv.z * w2.x + uv.w * w3.x;
            acc[rr][1] += uv.x * w0.y + uv.y * w1.y + uv.z * w2.y + uv.w * w3.y;
            acc[rr][2] += uv.x * w0.z + uv.y * w1.z + uv.z * w2.z + uv.w * w3.z;
            acc[rr][3] += uv.x * w0.w + uv.y * w1.w + uv.z * w2.w + uv.w * w3.w;
        }
    }

    float wl01[2] = {0.f, 0.f};
#pragma unroll
    for (int rr = 0; rr < 8; rr++) {
        int row = r0 + rr;
        float wl = 0.f;
#pragma unroll
        for (int c = 0; c < 4; c++) {
            int j = lane * 4 + c;
            wl += tanhf(acc[rr][c] + bsh[j]) * w2sh[j];
        }
        if (row < rows) wl01[row & 1] += wl;
    }
#pragma unroll
    for (int off = 16; off; off >>= 1) {
        wl01[0] += __shfl_xor_sync(0xffffffffu, wl01[0], off);
        wl01[1] += __shfl_xor_sync(0xffffffffu, wl01[1], off);
    }
    if (lane == 0) {
        atomicAdd(&wacc[0], wl01[0]);
        atomicAdd(&wacc[1], wl01[1]);
    }
    __syncthreads();
    if (tid < 2) atomicAdd(&g_wsum[wbase + tid], wacc[tid]);
}

// ---------------- final combine ----------------
__global__ void __launch_bounds__(256) k_combine(float* __restrict__ out) {
    unsigned i = blockIdx.x * 256u + threadIdx.x;
    if (i >= (unsigned)(NN * DD)) return;
    unsigned node = i >> 6, d = i & 63u;
    float w0, w1;
    size_t zr;
    if (node < NU) {
        w0 = g_wsum[0] * (1.f / NU);
        w1 = g_wsum[1] * (1.f / NU);
        zr = (size_t)node * 128;
    } else {
        w0 = g_wsum[2] * (1.f / NI);
        w1 = g_wsum[3] * (1.f / NI);
        zr = (size_t)NU * 128 + (size_t)(node - NU) * 128;
    }
    float mx = fmaxf(w0, w1);
    float e0 = __expf(w0 - mx), e1 = __expf(w1 - mx);
    float inv = 1.f / (e0 + e1);
    float han = (e0 * inv) * g_z[zr + d] + (e1 * inv) * g_z[zr + 64 + d];
    out[i] = 0.5f * g_total[i] + 0.5f * han;
}

// ---------------- launcher ----------------
extern "C" void kernel_launch(void* const* d_in, const int* in_sizes, int n_in,
                              void* d_out, int out_size) {
    const int*   G    = (const int*)d_in[0];
    const float* Gv   = (const float*)d_in[1];
    const float* fu   = (const float*)d_in[2];
    const float* fi   = (const float*)d_in[3];
    const float* Wu   = (const float*)d_in[4];
    const float* Wi   = (const float*)d_in[5];
    const int*   eu   = (const int*)d_in[6];
    const int*   ei   = (const int*)d_in[7];
    const float* suW1 = (const float*)d_in[8];
    const float* sub1 = (const float*)d_in[9];
    const float* suw2 = (const float*)d_in[10];
    const float* siW1 = (const float*)d_in[11];
    const float* sib1 = (const float*)d_in[12];
    const float* siw2 = (const float*)d_in[13];
    float* out = (float*)d_out;

    cudaFuncSetAttribute(k_intent, cudaFuncAttributeMaxDynamicSharedMemorySize, INTENT_SMEM);

    const int UB = (NU + IT_ROWS_PER_BLOCK - 1) / IT_ROWS_PER_BLOCK;  // 1563
    const int IB = (NI + IT_ROWS_PER_BLOCK - 1) / IT_ROWS_PER_BLOCK;  // 782

    // init + CSR build
    k_zero_cnt<<<1172, 256>>>();
    k_init<<<37500, 256>>>(fu, fi);
    k_histG<<<12500, 256>>>(G);
    k_histH<<<12500, 256>>>(eu, EU_, NU, 0);
    k_histH<<<6250, 256>>>(ei, EI_, NI, 2 * NU);
    k_scan<<<5, 1024>>>();
    k_fillG<<<12500, 256>>>(G, Gv);
    k_fillH<<<12500, 256>>>(eu, EU_, NU, 0, 0, 0);
    k_fillH<<<6250, 256>>>(ei, EI_, NI, 2 * NU, 2 * (NU + 1), 2 * EU_);

    // DCCF layers
    for (int layer = 0; layer < 2; layer++) {
        k_spmm_csr<<<9375, 256>>>();
        k_intent<<<UB + IB, IT_THREADS, INTENT_SMEM>>>(Wu, Wi);
    }

    // HAN
    k_hgather<<<12500, 256>>>(fu, EU_, NU, 0, 0, 0, 0);
    k_hgather<<<6250, 256>>>(fi, EI_, NI, 2 * NU, 2 * (NU + 1), 2 * EU_, NU * 128);
    k_han_node<<<3125, 256>>>(suW1, sub1, suw2, NU, 0, 0);
    k_han_node<<<1563, 256>>>(siW1, sib1, siw2, NI, NU * 128, 2);
    k_combine<<<37500, 256>>>(out);
}

// round 9
// speedup vs baseline: 1.3080x; 1.0097x over previous
#include <cuda_runtime.h>

#define NU 100000
#define NI 50000
#define NN 150000
#define DD 64
#define EG 3200000
#define EU_ 1600000
#define EI_ 800000

typedef unsigned long long ull;

// ---------------- device scratch ----------------
__device__ float g_cur[NN * DD];
__device__ float g_gnn[NN * DD];
__device__ float g_total[NN * DD];
__device__ float g_z[NN * 2 * DD];        // row = node*2 + metapath
__device__ float g_wsum[4];

// CSR for G
__device__ int    g_cntG[NN];
__device__ int    g_curG[NN];
__device__ int    g_rptrG[NN + 1];
__device__ float2 g_epayG[EG];            // {col_bits, val}

// CSR + degrees for HAN (4 graphs: u-mp0, u-mp1, i-mp0, i-mp1)
#define HN (2 * NU + 2 * NI)
__device__ int g_dout[HN];
__device__ int g_din[HN];
__device__ int g_curH[HN];
__device__ int g_rptrH[2 * (NU + 1) + 2 * (NI + 1)];
__device__ int g_hpay[2 * EU_ + 2 * EI_];

// f32x2 packed math (sm_100+)
__device__ __forceinline__ ull pk2(float a) {
    ull r;
    asm("mov.b64 %0, {%1, %1};" : "=l"(r) : "f"(a));
    return r;
}
__device__ __forceinline__ ull pack2(float lo, float hi) {
    ull r;
    asm("mov.b64 %0, {%1, %2};" : "=l"(r) : "f"(lo), "f"(hi));
    return r;
}
__device__ __forceinline__ void fma2(ull& d, ull a, ull b) {
    asm("fma.rn.f32x2 %0, %1, %2, %0;" : "+l"(d) : "l"(a), "l"(b));
}
__device__ __forceinline__ float2 up2(ull v) {
    float2 f;
    asm("mov.b64 {%0, %1}, %2;" : "=f"(f.x), "=f"(f.y) : "l"(v));
    return f;
}

// ---------------- zero counters ----------------
__global__ void __launch_bounds__(256) k_zero_cnt() {
    unsigned i = blockIdx.x * 256u + threadIdx.x;
    if (i < NN) { g_cntG[i] = 0; g_curG[i] = 0; }
    if (i < HN) { g_dout[i] = 0; g_din[i] = 0; g_curH[i] = 0; }
    if (i < 4u) g_wsum[i] = 0.f;
}

// ---------------- init ----------------
__global__ void __launch_bounds__(256) k_init(const float* __restrict__ fu,
                                              const float* __restrict__ fi) {
    unsigned i = blockIdx.x * 256u + threadIdx.x;
    if (i < NU * DD) {
        float v = fu[i];
        g_cur[i] = v; g_total[i] = v;
    } else if (i < NN * DD) {
        float v = fi[i - NU * DD];
        g_cur[i] = v; g_total[i] = v;
    }
}

// ---------------- CSR build ----------------
__global__ void __launch_bounds__(256) k_histG(const int* __restrict__ G) {
    unsigned e = blockIdx.x * 256u + threadIdx.x;
    if (e >= EG) return;
    atomicAdd(&g_cntG[__ldg(G + e)], 1);
}

__global__ void __launch_bounds__(256) k_histH(const int* __restrict__ edges, int E2,
                                               int n, int base) {
    unsigned t = blockIdx.x * 256u + threadIdx.x;
    if (t >= 2u * (unsigned)E2) return;
    int m = (t >= (unsigned)E2) ? 1 : 0;
    int e = (int)t - m * E2;
    int src = __ldg(edges + (size_t)m * 2 * E2 + e);
    int dst = __ldg(edges + (size_t)m * 2 * E2 + E2 + e);
    atomicAdd(&g_dout[base + m * n + src], 1);
    atomicAdd(&g_din[base + m * n + dst], 1);
}

__device__ __forceinline__ void scan_impl(const int* cnt, int* rptr, int n) {
    __shared__ int wsum[32];
    __shared__ int s_carry;
    const int tid = threadIdx.x, lane = tid & 31, wid = tid >> 5;
    if (tid == 0) s_carry = 0;
    __syncthreads();
    for (int base = 0; base < n; base += 1024) {
        int i = base + tid;
        int v = (i < n) ? cnt[i] : 0;
        int x = v;
#pragma unroll
        for (int off = 1; off < 32; off <<= 1) {
            int y = __shfl_up_sync(0xffffffffu, x, off);
            if (lane >= off) x += y;
        }
        if (lane == 31) wsum[wid] = x;
        __syncthreads();
        if (wid == 0) {
            int s = wsum[lane];
#pragma unroll
            for (int off = 1; off < 32; off <<= 1) {
                int y = __shfl_up_sync(0xffffffffu, s, off);
                if (lane >= off) s += y;
            }
            wsum[lane] = s;
        }
        __syncthreads();
        int excl = x - v + (wid > 0 ? wsum[wid - 1] : 0) + s_carry;
        int ctot = wsum[31];
        if (i < n) rptr[i] = excl;
        __syncthreads();
        if (tid == 0) s_carry += ctot;
        __syncthreads();
    }
    if (tid == 0) rptr[n] = s_carry;
}

__global__ void __launch_bounds__(1024) k_scanG() {
    scan_impl(g_cntG, g_rptrG, NN);
}

__global__ void __launch_bounds__(1024) k_scanH() {
    const int* cnt; int* rptr; int n;
    switch (blockIdx.x) {
        case 0:  cnt = g_din;               rptr = g_rptrH;                            n = NU; break;
        case 1:  cnt = g_din + NU;          rptr = g_rptrH + (NU + 1);                 n = NU; break;
        case 2:  cnt = g_din + 2 * NU;      rptr = g_rptrH + 2 * (NU + 1);             n = NI; break;
        default: cnt = g_din + 2 * NU + NI; rptr = g_rptrH + 2 * (NU + 1) + (NI + 1);  n = NI; break;
    }
    scan_impl(cnt, rptr, n);
}

__global__ void __launch_bounds__(256) k_fillG(const int* __restrict__ G,
                                               const float* __restrict__ gv) {
    unsigned e = blockIdx.x * 256u + threadIdx.x;
    if (e >= EG) return;
    int row = __ldg(G + e);
    int col = __ldg(G + EG + e);
    float v = __ldg(gv + e);
    int pos = g_rptrG[row] + atomicAdd(&g_curG[row], 1);
    g_epayG[pos] = make_float2(__int_as_float(col), v);
}

__global__ void __launch_bounds__(256) k_fillH(const int* __restrict__ edges, int E2,
                                               int n, int base, int rbase, int paybase) {
    unsigned t = blockIdx.x * 256u + threadIdx.x;
    if (t >= 2u * (unsigned)E2) return;
    int m = (t >= (unsigned)E2) ? 1 : 0;
    int e = (int)t - m * E2;
    int src = __ldg(edges + (size_t)m * 2 * E2 + e);
    int dst = __ldg(edges + (size_t)m * 2 * E2 + E2 + e);
    const int* rptr = g_rptrH + rbase + m * (n + 1);
    int pos = rptr[dst] + atomicAdd(&g_curH[base + m * n + dst], 1);
    g_hpay[paybase + m * E2 + pos] = src;
}

// ---------------- DCCF: CSR SpMM ----------------
__global__ void __launch_bounds__(256) k_spmm_csr() {
    unsigned t = blockIdx.x * 256u + threadIdx.x;
    unsigned r = t >> 4;
    unsigned c = t & 15u;
    if (r >= NN) return;
    int s = g_rptrG[r], e = g_rptrG[r + 1];
    float4 acc = make_float4(0.f, 0.f, 0.f, 0.f);
    int i = s;
    for (; i + 2 <= e; i += 2) {
        float2 p0 = __ldg(&g_epayG[i]);
        float2 p1 = __ldg(&g_epayG[i + 1]);
        int c0 = __float_as_int(p0.x), c1 = __float_as_int(p1.x);
        float4 x0 = *(const float4*)(g_cur + (size_t)c0 * DD + c * 4);
        float4 x1 = *(const float4*)(g_cur + (size_t)c1 * DD + c * 4);
        acc.x += p0.y * x0.x + p1.y * x1.x;
        acc.y += p0.y * x0.y + p1.y * x1.y;
        acc.z += p0.y * x0.z + p1.y * x1.z;
        acc.w += p0.y * x0.w + p1.y * x1.w;
    }
    if (i < e) {
        float2 p0 = __ldg(&g_epayG[i]);
        int c0 = __float_as_int(p0.x);
        float4 x0 = *(const float4*)(g_cur + (size_t)c0 * DD + c * 4);
        acc.x += p0.y * x0.x; acc.y += p0.y * x0.y;
        acc.z += p0.y * x0.z; acc.w += p0.y * x0.w;
    }
    *(float4*)(g_gnn + (size_t)r * DD + c * 4) = acc;
}

// ---------------- DCCF: intent — f32x2 row-pair (R8 layout) ----------------
#define INTENT_SMEM 82944
#define IT_THREADS 256
#define IT_ROWS_PER_BLOCK 64

__global__ void __launch_bounds__(IT_THREADS) k_intent(const float* __restrict__ Wu,
                                                       const float* __restrict__ Wi) {
    extern __shared__ float sm[];
    float2* WTpw = (float2*)sm;
    const float2* WTp = (const float2*)sm;
    const int tid = threadIdx.x, w = tid >> 5, lane = tid & 31;

    ull* uT2 = (ull*)(sm + 8448) + w * 256;
    ull* pT2 = (ull*)(sm + 12544) + w * 512;

    const int UB = (NU + IT_ROWS_PER_BLOCK - 1) / IT_ROWS_PER_BLOCK;  // 1563
    const bool isUser = (int)blockIdx.x < UB;
    const float* Wg = isUser ? Wu : Wi;
    const int rowbase = isUser ? (int)blockIdx.x * IT_ROWS_PER_BLOCK
                               : NU + ((int)blockIdx.x - UB) * IT_ROWS_PER_BLOCK;
    const int rowlim = isUser ? NU : NN;

    for (int t = tid; t < 4096; t += IT_THREADS) {
        int L = t >> 7, j = t & 127;
        WTpw[j * 33 + L] = make_float2(Wg[(2 * L) * 128 + j], Wg[(2 * L + 1) * 128 + j]);
    }
    __syncthreads();

    const int r0 = rowbase + w * 8;

    for (int t = lane; t < 256; t += 32) {
        int rho = t >> 6, k = t & 63;
        int ra = r0 + 2 * rho, rb = ra + 1;
        float xa = (ra < rowlim) ? g_cur[(size_t)ra * DD + k] : 0.f;
        float xb = (rb < rowlim) ? g_cur[(size_t)rb * DD + k] : 0.f;
        uT2[rho * 64 + k] = pack2(xa, xb);
    }
    __syncwarp();

    ull acc[4][4];
#pragma unroll
    for (int a = 0; a < 4; a++) { acc[a][0] = acc[a][1] = acc[a][2] = acc[a][3] = 0ull; }

    const ulonglong2* uT2v = (const ulonglong2*)uT2;
#pragma unroll 4
    for (int L = 0; L < 32; L++) {
        float2 w0 = WTp[(lane +  0) * 33 + L];
        float2 w1 = WTp[(lane + 32) * 33 + L];
        float2 w2 = WTp[(lane + 64) * 33 + L];
        float2 w3 = WTp[(lane + 96) * 33 + L];
        ull s0x = pk2(w0.x), s0y = pk2(w0.y);
        ull s1x = pk2(w1.x), s1y = pk2(w1.y);
        ull s2x = pk2(w2.x), s2y = pk2(w2.y);
        ull s3x = pk2(w3.x), s3y = pk2(w3.y);
#pragma unroll
        for (int rho = 0; rho < 4; rho++) {
            ulonglong2 up = uT2v[rho * 32 + L];
            fma2(acc[rho][0], s0x, up.x); fma2(acc[rho][0], s0y, up.y);
            fma2(acc[rho][1], s1x, up.x); fma2(acc[rho][1], s1y, up.y);
            fma2(acc[rho][2], s2x, up.x); fma2(acc[rho][2], s2y, up.y);
            fma2(acc[rho][3], s3x, up.x); fma2(acc[rho][3], s3y, up.y);
        }
    }

#pragma unroll
    for (int rho = 0; rho < 4; rho++) {
        float2 a0 = up2(acc[rho][0]), a1 = up2(acc[rho][1]);
        float2 a2 = up2(acc[rho][2]), a3 = up2(acc[rho][3]);
        float ml = fmaxf(fmaxf(a0.x, a1.x), fmaxf(a2.x, a3.x));
        float mh = fmaxf(fmaxf(a0.y, a1.y), fmaxf(a2.y, a3.y));
#pragma unroll
        for (int off = 16; off; off >>= 1) {
            ml = fmaxf(ml, __shfl_xor_sync(0xffffffffu, ml, off));
            mh = fmaxf(mh, __shfl_xor_sync(0xffffffffu, mh, off));
        }
        float el0 = __expf(a0.x - ml), el1 = __expf(a1.x - ml);
        float el2 = __expf(a2.x - ml), el3 = __expf(a3.x - ml);
        float eh0 = __expf(a0.y - mh), eh1 = __expf(a1.y - mh);
        float eh2 = __expf(a2.y - mh), eh3 = __expf(a3.y - mh);
        float sl = el0 + el1 + el2 + el3;
        float sh = eh0 + eh1 + eh2 + eh3;
#pragma unroll
        for (int off = 16; off; off >>= 1) {
            sl += __shfl_xor_sync(0xffffffffu, sl, off);
            sh += __shfl_xor_sync(0xffffffffu, sh, off);
        }
        float il = 1.f / sl, ih = 1.f / sh;
        pT2[rho * 128 + lane +  0] = pack2(el0 * il, eh0 * ih);
        pT2[rho * 128 + lane + 32] = pack2(el1 * il, eh1 * ih);
        pT2[rho * 128 + lane + 64] = pack2(el2 * il, eh2 * ih);
        pT2[rho * 128 + lane + 96] = pack2(el3 * il, eh3 * ih);
    }
    __syncwarp();

    ull acc2[4][2];
#pragma unroll
    for (int a = 0; a < 4; a++) { acc2[a][0] = 0ull; acc2[a][1] = 0ull; }

    const ulonglong2* pT2v = (const ulonglong2*)pT2;
#pragma unroll 2
    for (int j4 = 0; j4 < 32; j4++) {
        ulonglong2 P0a = pT2v[0 * 64 + 2 * j4], P0b = pT2v[0 * 64 + 2 * j4 + 1];
        ulonglong2 P1a = pT2v[1 * 64 + 2 * j4], P1b = pT2v[1 * 64 + 2 * j4 + 1];
        ulonglong2 P2a = pT2v[2 * 64 + 2 * j4], P2b = pT2v[2 * 64 + 2 * j4 + 1];
        ulonglong2 P3a = pT2v[3 * 64 + 2 * j4], P3b = pT2v[3 * 64 + 2 * j4 + 1];
#define P2J(JJ, PW)                                             \
        {                                                       \
            float2 wt = WTp[(4 * j4 + JJ) * 33 + lane];         \
            ull s0 = pk2(wt.x), s1 = pk2(wt.y);                 \
            fma2(acc2[0][0], s0, P0##PW); fma2(acc2[0][1], s1, P0##PW); \
            fma2(acc2[1][0], s0, P1##PW); fma2(acc2[1][1], s1, P1##PW); \
            fma2(acc2[2][0], s0, P2##PW); fma2(acc2[2][1], s1, P2##PW); \
            fma2(acc2[3][0], s0, P3##PW); fma2(acc2[3][1], s1, P3##PW); \
        }
        P2J(0, a.x) P2J(1, a.y) P2J(2, b.x) P2J(3, b.y)
#undef P2J
    }

#pragma unroll
    for (int rho = 0; rho < 4; rho++) {
        float2 o0 = up2(acc2[rho][0]);
        float2 o1 = up2(acc2[rho][1]);
#pragma unroll
        for (int par = 0; par < 2; par++) {
            int r = r0 + 2 * rho + par;
            if (r >= rowlim) continue;
            float oa = par ? o0.y : o0.x;
            float ob = par ? o1.y : o1.x;
            size_t base = (size_t)r * DD + lane * 2;
            float2 cu = *(const float2*)(g_cur + base);
            float2 gn = *(const float2*)(g_gnn + base);
            float2 tt = *(const float2*)(g_total + base);
            float n0 = gn.x + oa + cu.x;
            float n1 = gn.y + ob + cu.y;
            *(float2*)(g_cur + base) = make_float2(n0, n1);
            *(float2*)(g_total + base) = make_float2(tt.x + n0, tt.y + n1);
        }
    }
}

// ---------------- HAN: CSR gather ----------------
__global__ void __launch_bounds__(256) k_hgather(const float* __restrict__ feat, int E2,
                                                 int n, int base, int rbase, int paybase,
                                                 int zbase) {
    unsigned t = blockIdx.x * 256u + threadIdx.x;
    unsigned idx = t >> 4;
    unsigned c = t & 15u;
    if (idx >= 2u * (unsigned)n) return;
    int m = (idx >= (unsigned)n) ? 1 : 0;
    int node = (int)idx - m * n;
    const int* rptr = g_rptrH + rbase + m * (n + 1);
    int s = rptr[node], e = rptr[node + 1];
    const int* pay = g_hpay + paybase + m * E2;
    const int* dout = g_dout + base + m * n;
    float4 acc = make_float4(0.f, 0.f, 0.f, 0.f);
    int i = s;
    for (; i + 2 <= e; i += 2) {
        int s0 = __ldg(pay + i), s1 = __ldg(pay + i + 1);
        float w0 = rsqrtf((float)__ldg(dout + s0));
        float w1 = rsqrtf((float)__ldg(dout + s1));
        float4 x0 = *(const float4*)(feat + (size_t)s0 * DD + c * 4);
        float4 x1 = *(const float4*)(feat + (size_t)s1 * DD + c * 4);
        acc.x += w0 * x0.x + w1 * x1.x;
        acc.y += w0 * x0.y + w1 * x1.y;
        acc.z += w0 * x0.z + w1 * x1.z;
        acc.w += w0 * x0.w + w1 * x1.w;
    }
    if (i < e) {
        int s0 = __ldg(pay + i);
        float w0 = rsqrtf((float)__ldg(dout + s0));
        float4 x0 = *(const float4*)(feat + (size_t)s0 * DD + c * 4);
        acc.x += w0 * x0.x; acc.y += w0 * x0.y;
        acc.z += w0 * x0.z; acc.w += w0 * x0.w;
    }
    float din = (float)(e - s);
    float sc = (din > 0.f) ? rsqrtf(din) : 0.f;
    *(float4*)(g_z + (size_t)zbase + ((size_t)node * 2 + m) * DD + c * 4) =
        make_float4(acc.x * sc, acc.y * sc, acc.z * sc, acc.w * sc);
}

// ---------------- HAN: semantic attention logits ----------------
__global__ void __launch_bounds__(256) k_han_node(const float* __restrict__ W1g,
                                                  const float* __restrict__ b1g,
                                                  const float* __restrict__ w2g,
                                                  int n, int zbase, int wbase) {
    __shared__ float Wsm[8192];
    __shared__ float ush[4096];
    __shared__ float bsh[128];
    __shared__ float w2sh[128];
    __shared__ float wacc[2];

    const int tid = threadIdx.x, w = tid >> 5, lane = tid & 31;
    for (int t = tid; t < 2048; t += 256) {
        int k = t >> 5, L = t & 31;
        ((float4*)Wsm)[t] = *(const float4*)(W1g + k * 128 + L * 4);
    }
    if (tid < 128) { bsh[tid] = b1g[tid]; w2sh[tid] = w2g[tid]; }
    if (tid < 2) wacc[tid] = 0.f;
    __syncthreads();

    const int rows = 2 * n;
    const int r0 = (int)blockIdx.x * 64 + w * 8;
    float* u = ush + w * 512;

    for (int t = lane; t < 512; t += 32) {
        int rr = t >> 6, d = t & 63;
        int row = r0 + rr;
        u[t] = (row < rows) ? g_z[(size_t)zbase + (size_t)row * DD + d] : 0.f;
    }
    __syncwarp();

    float acc[8][4];
#pragma unroll
    for (int a = 0; a < 8; a++) { acc[a][0] = acc[a][1] = acc[a][2] = acc[a][3] = 0.f; }

#pragma unroll 2
    for (int kk = 0; kk < 16; kk++) {
        float4 w0 = ((const float4*)Wsm)[(4 * kk + 0) * 32 + lane];
        float4 w1 = ((const float4*)Wsm)[(4 * kk + 1) * 32 + lane];
        float4 w2 = ((const float4*)Wsm)[(4 * kk + 2) * 32 + lane];
        float4 w3 = ((const float4*)Wsm)[(4 * kk + 3) * 32 + lane];
#pragma unroll
        for (int rr = 0; rr < 8; rr++) {
            float4 uv = *(const float4*)(u + rr * 64 + kk * 4);
            acc[rr][0] += uv.x * w0.x + uv.y * w1.x + uv.z * w2.x + uv.w * w3.x;
            acc[rr][1] += uv.x * w0.y + uv.y * w1.y + uv.z * w2.y + uv.w * w3.y;
            acc[rr][2] += uv.x * w0.z + uv.y * w1.z + uv.z * w2.z + uv.w * w3.z;
            acc[rr][3] += uv.x * w0.w + uv.y * w1.w + uv.z * w2.w + uv.w * w3.w;
        }
    }

    float wl01[2] = {0.f, 0.f};
#pragma unroll
    for (int rr = 0; rr < 8; rr++) {
        int row = r0 + rr;
        float wl = 0.f;
#pragma unroll
        for (int c = 0; c < 4; c++) {
            int j = lane * 4 + c;
            wl += tanhf(acc[rr][c] + bsh[j]) * w2sh[j];
        }
        if (row < rows) wl01[row & 1] += wl;
    }
#pragma unroll
    for (int off = 16; off; off >>= 1) {
        wl01[0] += __shfl_xor_sync(0xffffffffu, wl01[0], off);
        wl01[1] += __shfl_xor_sync(0xffffffffu, wl01[1], off);
    }
    if (lane == 0) {
        atomicAdd(&wacc[0], wl01[0]);
        atomicAdd(&wacc[1], wl01[1]);
    }
    __syncthreads();
    if (tid < 2) atomicAdd(&g_wsum[wbase + tid], wacc[tid]);
}

// ---------------- final combine ----------------
__global__ void __launch_bounds__(256) k_combine(float* __restrict__ out) {
    unsigned i = blockIdx.x * 256u + threadIdx.x;
    if (i >= (unsigned)(NN * DD)) return;
    unsigned node = i >> 6, d = i & 63u;
    float w0, w1;
    size_t zr;
    if (node < NU) {
        w0 = g_wsum[0] * (1.f / NU);
        w1 = g_wsum[1] * (1.f / NU);
        zr = (size_t)node * 128;
    } else {
        w0 = g_wsum[2] * (1.f / NI);
        w1 = g_wsum[3] * (1.f / NI);
        zr = (size_t)NU * 128 + (size_t)(node - NU) * 128;
    }
    float mx = fmaxf(w0, w1);
    float e0 = __expf(w0 - mx), e1 = __expf(w1 - mx);
    float inv = 1.f / (e0 + e1);
    float han = (e0 * inv) * g_z[zr + d] + (e1 * inv) * g_z[zr + 64 + d];
    out[i] = 0.5f * g_total[i] + 0.5f * han;
}

// ---------------- launcher: DCCF on stream0, HAN on side stream ----------------
extern "C" void kernel_launch(void* const* d_in, const int* in_sizes, int n_in,
                              void* d_out, int out_size) {
    const int*   G    = (const int*)d_in[0];
    const float* Gv   = (const float*)d_in[1];
    const float* fu   = (const float*)d_in[2];
    const float* fi   = (const float*)d_in[3];
    const float* Wu   = (const float*)d_in[4];
    const float* Wi   = (const float*)d_in[5];
    const int*   eu   = (const int*)d_in[6];
    const int*   ei   = (const int*)d_in[7];
    const float* suW1 = (const float*)d_in[8];
    const float* sub1 = (const float*)d_in[9];
    const float* suw2 = (const float*)d_in[10];
    const float* siW1 = (const float*)d_in[11];
    const float* sib1 = (const float*)d_in[12];
    const float* siw2 = (const float*)d_in[13];
    float* out = (float*)d_out;

    static cudaStream_t s_han = nullptr;
    static cudaEvent_t ev_fork = nullptr, ev_join = nullptr;
    if (!s_han) {
        cudaStreamCreateWithFlags(&s_han, cudaStreamNonBlocking);
        cudaEventCreateWithFlags(&ev_fork, cudaEventDisableTiming);
        cudaEventCreateWithFlags(&ev_join, cudaEventDisableTiming);
        cudaFuncSetAttribute(k_intent, cudaFuncAttributeMaxDynamicSharedMemorySize,
                             INTENT_SMEM);
    }

    const int UB = (NU + IT_ROWS_PER_BLOCK - 1) / IT_ROWS_PER_BLOCK;  // 1563
    const int IB = (NI + IT_ROWS_PER_BLOCK - 1) / IT_ROWS_PER_BLOCK;  // 782

    // common prologue on main stream
    k_zero_cnt<<<1172, 256>>>();
    cudaEventRecord(ev_fork, 0);

    // ---- HAN chain on side stream ----
    cudaStreamWaitEvent(s_han, ev_fork, 0);
    k_histH<<<12500, 256, 0, s_han>>>(eu, EU_, NU, 0);
    k_histH<<<6250, 256, 0, s_han>>>(ei, EI_, NI, 2 * NU);
    k_scanH<<<4, 1024, 0, s_han>>>();
    k_fillH<<<12500, 256, 0, s_han>>>(eu, EU_, NU, 0, 0, 0);
    k_fillH<<<6250, 256, 0, s_han>>>(ei, EI_, NI, 2 * NU, 2 * (NU + 1), 2 * EU_);
    k_hgather<<<12500, 256, 0, s_han>>>(fu, EU_, NU, 0, 0, 0, 0);
    k_hgather<<<6250, 256, 0, s_han>>>(fi, EI_, NI, 2 * NU, 2 * (NU + 1), 2 * EU_, NU * 128);
    k_han_node<<<3125, 256, 0, s_han>>>(suW1, sub1, suw2, NU, 0, 0);
    k_han_node<<<1563, 256, 0, s_han>>>(siW1, sib1, siw2, NI, NU * 128, 2);
    cudaEventRecord(ev_join, s_han);

    // ---- DCCF chain on main stream ----
    k_init<<<37500, 256>>>(fu, fi);
    k_histG<<<12500, 256>>>(G);
    k_scanG<<<1, 1024>>>();
    k_fillG<<<12500, 256>>>(G, Gv);
    for (int layer = 0; layer < 2; layer++) {
        k_spmm_csr<<<9375, 256>>>();
        k_intent<<<UB + IB, IT_THREADS, INTENT_SMEM>>>(Wu, Wi);
    }

    // ---- join + combine ----
    cudaStreamWaitEvent(0, ev_join, 0);
    k_combine<<<37500, 256>>>(out);
}

// round 10
// speedup vs baseline: 1.4713x; 1.1248x over previous
#include <cuda_runtime.h>

#define NU 100000
#define NI 50000
#define NN 150000
#define DD 64
#define EG 3200000
#define EU_ 1600000
#define EI_ 800000

typedef unsigned long long ull;

// ---------------- device scratch ----------------
__device__ float g_cur[NN * DD];
__device__ float g_gnn[NN * DD];
__device__ float g_total[NN * DD];
__device__ float g_z[NN * 2 * DD];
__device__ float g_wsum[4];

// CSR for G
__device__ int    g_cntG[NN];
__device__ int    g_curG[NN];
__device__ int    g_rptrG[NN + 1];
__device__ float2 g_epayG[EG];

// CSR + degrees for HAN
#define HN (2 * NU + 2 * NI)
__device__ int g_dout[HN];
__device__ int g_din[HN];
__device__ int g_curH[HN];
__device__ int g_rptrH[2 * (NU + 1) + 2 * (NI + 1)];
__device__ int g_hpay[2 * EU_ + 2 * EI_];

// block-sum scratch for parallel scans
#define NB_G 147                 // ceil(150000/1024)
#define NB_HU 98                 // ceil(100000/1024)
#define NB_HI 49                 // ceil(50000/1024)
__device__ int g_bsumG[NB_G];
__device__ int g_bsumH[4 * NB_HU];   // seg s at s*NB_HU

// f32x2 packed math (sm_100+)
__device__ __forceinline__ ull pk2(float a) {
    ull r;
    asm("mov.b64 %0, {%1, %1};" : "=l"(r) : "f"(a));
    return r;
}
__device__ __forceinline__ ull pack2(float lo, float hi) {
    ull r;
    asm("mov.b64 %0, {%1, %2};" : "=l"(r) : "f"(lo), "f"(hi));
    return r;
}
__device__ __forceinline__ void fma2(ull& d, ull a, ull b) {
    asm("fma.rn.f32x2 %0, %1, %2, %0;" : "+l"(d) : "l"(a), "l"(b));
}
__device__ __forceinline__ float2 up2(ull v) {
    float2 f;
    asm("mov.b64 {%0, %1}, %2;" : "=f"(f.x), "=f"(f.y) : "l"(v));
    return f;
}

// ---------------- zero counters ----------------
__global__ void __launch_bounds__(256) k_zero_cnt() {
    unsigned i = blockIdx.x * 256u + threadIdx.x;
    if (i < NN) { g_cntG[i] = 0; g_curG[i] = 0; }
    if (i < HN) { g_dout[i] = 0; g_din[i] = 0; g_curH[i] = 0; }
    if (i < 4u) g_wsum[i] = 0.f;
}

// ---------------- init ----------------
__global__ void __launch_bounds__(256) k_init(const float* __restrict__ fu,
                                              const float* __restrict__ fi) {
    unsigned i = blockIdx.x * 256u + threadIdx.x;
    if (i < NU * DD) {
        float v = fu[i];
        g_cur[i] = v; g_total[i] = v;
    } else if (i < NN * DD) {
        float v = fi[i - NU * DD];
        g_cur[i] = v; g_total[i] = v;
    }
}

// ---------------- histograms ----------------
__global__ void __launch_bounds__(256) k_histG(const int* __restrict__ G) {
    unsigned e = blockIdx.x * 256u + threadIdx.x;
    if (e >= EG) return;
    atomicAdd(&g_cntG[__ldg(G + e)], 1);
}

__global__ void __launch_bounds__(256) k_histH(const int* __restrict__ edges, int E2,
                                               int n, int base) {
    unsigned t = blockIdx.x * 256u + threadIdx.x;
    if (t >= 2u * (unsigned)E2) return;
    int m = (t >= (unsigned)E2) ? 1 : 0;
    int e = (int)t - m * E2;
    int src = __ldg(edges + (size_t)m * 2 * E2 + e);
    int dst = __ldg(edges + (size_t)m * 2 * E2 + E2 + e);
    atomicAdd(&g_dout[base + m * n + src], 1);
    atomicAdd(&g_din[base + m * n + dst], 1);
}

// ---------------- parallel scans: block-scan, sum-scan, add ----------------
__device__ __forceinline__ int blockscan_1024(int v, int* ws) {
    const int tid = threadIdx.x, lane = tid & 31, wid = tid >> 5;
    int x = v;
#pragma unroll
    for (int off = 1; off < 32; off <<= 1) {
        int y = __shfl_up_sync(0xffffffffu, x, off);
        if (lane >= off) x += y;
    }
    if (lane == 31) ws[wid] = x;
    __syncthreads();
    if (wid == 0) {
        int s = ws[lane];
#pragma unroll
        for (int off = 1; off < 32; off <<= 1) {
            int y = __shfl_up_sync(0xffffffffu, s, off);
            if (lane >= off) s += y;
        }
        ws[lane] = s;
    }
    __syncthreads();
    return x - v + (wid > 0 ? ws[wid - 1] : 0);   // exclusive within block
}

__global__ void __launch_bounds__(1024) k_scanG1() {
    __shared__ int ws[32];
    int i = blockIdx.x * 1024 + threadIdx.x;
    int v = (i < NN) ? g_cntG[i] : 0;
    int excl = blockscan_1024(v, ws);
    if (i < NN) g_rptrG[i] = excl;
    if (threadIdx.x == 0) g_bsumG[blockIdx.x] = ws[31];
}

__global__ void __launch_bounds__(32) k_scanG2() {
    int lane = threadIdx.x;
    int carry = 0;
    for (int base = 0; base < NB_G; base += 32) {
        int idx = base + lane;
        int v = (idx < NB_G) ? g_bsumG[idx] : 0;
        int x = v;
#pragma unroll
        for (int off = 1; off < 32; off <<= 1) {
            int y = __shfl_up_sync(0xffffffffu, x, off);
            if (lane >= off) x += y;
        }
        if (idx < NB_G) g_bsumG[idx] = x - v + carry;
        carry += __shfl_sync(0xffffffffu, x, 31);
    }
    if (lane == 0) g_rptrG[NN] = carry;
}

__global__ void __launch_bounds__(1024) k_scanG3() {
    int i = blockIdx.x * 1024 + threadIdx.x;
    if (i < NN) g_rptrG[i] += g_bsumG[blockIdx.x];
}

__device__ __forceinline__ void hseg_decode(int b, int& seg, int& lb, int& n,
                                            const int*& cnt, int*& rptr) {
    if (b < NB_HU)           { seg = 0; lb = b; }
    else if (b < 2 * NB_HU)  { seg = 1; lb = b - NB_HU; }
    else if (b < 2 * NB_HU + NB_HI) { seg = 2; lb = b - 2 * NB_HU; }
    else                     { seg = 3; lb = b - 2 * NB_HU - NB_HI; }
    n = (seg < 2) ? NU : NI;
    cnt = g_din + (seg == 0 ? 0 : seg == 1 ? NU : seg == 2 ? 2 * NU : 2 * NU + NI);
    rptr = g_rptrH + (seg == 0 ? 0 : seg == 1 ? (NU + 1)
                      : seg == 2 ? 2 * (NU + 1) : 2 * (NU + 1) + (NI + 1));
}

__global__ void __launch_bounds__(1024) k_scanH1() {
    __shared__ int ws[32];
    int seg, lb, n; const int* cnt; int* rptr;
    hseg_decode(blockIdx.x, seg, lb, n, cnt, rptr);
    int i = lb * 1024 + threadIdx.x;
    int v = (i < n) ? cnt[i] : 0;
    int excl = blockscan_1024(v, ws);
    if (i < n) rptr[i] = excl;
    if (threadIdx.x == 0) g_bsumH[seg * NB_HU + lb] = ws[31];
}

__global__ void __launch_bounds__(128) k_scanH2() {
    int lane = threadIdx.x & 31, seg = threadIdx.x >> 5;
    int nb = (seg < 2) ? NB_HU : NB_HI;
    int n = (seg < 2) ? NU : NI;
    int* rptr = g_rptrH + (seg == 0 ? 0 : seg == 1 ? (NU + 1)
                           : seg == 2 ? 2 * (NU + 1) : 2 * (NU + 1) + (NI + 1));
    int* bs = g_bsumH + seg * NB_HU;
    int carry = 0;
    for (int base = 0; base < nb; base += 32) {
        int idx = base + lane;
        int v = (idx < nb) ? bs[idx] : 0;
        int x = v;
#pragma unroll
        for (int off = 1; off < 32; off <<= 1) {
            int y = __shfl_up_sync(0xffffffffu, x, off);
            if (lane >= off) x += y;
        }
        if (idx < nb) bs[idx] = x - v + carry;
        carry += __shfl_sync(0xffffffffu, x, 31);
    }
    if (lane == 0) rptr[n] = carry;
}

__global__ void __launch_bounds__(1024) k_scanH3() {
    int seg, lb, n; const int* cnt; int* rptr;
    hseg_decode(blockIdx.x, seg, lb, n, cnt, rptr);
    int i = lb * 1024 + threadIdx.x;
    if (i < n) rptr[i] += g_bsumH[seg * NB_HU + lb];
}

// ---------------- CSR fill ----------------
__global__ void __launch_bounds__(256) k_fillG(const int* __restrict__ G,
                                               const float* __restrict__ gv) {
    unsigned e = blockIdx.x * 256u + threadIdx.x;
    if (e >= EG) return;
    int row = __ldg(G + e);
    int col = __ldg(G + EG + e);
    float v = __ldg(gv + e);
    int pos = g_rptrG[row] + atomicAdd(&g_curG[row], 1);
    g_epayG[pos] = make_float2(__int_as_float(col), v);
}

__global__ void __launch_bounds__(256) k_fillH(const int* __restrict__ edges, int E2,
                                               int n, int base, int rbase, int paybase) {
    unsigned t = blockIdx.x * 256u + threadIdx.x;
    if (t >= 2u * (unsigned)E2) return;
    int m = (t >= (unsigned)E2) ? 1 : 0;
    int e = (int)t - m * E2;
    int src = __ldg(edges + (size_t)m * 2 * E2 + e);
    int dst = __ldg(edges + (size_t)m * 2 * E2 + E2 + e);
    const int* rptr = g_rptrH + rbase + m * (n + 1);
    int pos = rptr[dst] + atomicAdd(&g_curH[base + m * n + dst], 1);
    g_hpay[paybase + m * E2 + pos] = src;
}

// ---------------- DCCF: CSR SpMM ----------------
__global__ void __launch_bounds__(256) k_spmm_csr() {
    unsigned t = blockIdx.x * 256u + threadIdx.x;
    unsigned r = t >> 4;
    unsigned c = t & 15u;
    if (r >= NN) return;
    int s = g_rptrG[r], e = g_rptrG[r + 1];
    float4 acc = make_float4(0.f, 0.f, 0.f, 0.f);
    int i = s;
    for (; i + 2 <= e; i += 2) {
        float2 p0 = __ldg(&g_epayG[i]);
        float2 p1 = __ldg(&g_epayG[i + 1]);
        int c0 = __float_as_int(p0.x), c1 = __float_as_int(p1.x);
        float4 x0 = *(const float4*)(g_cur + (size_t)c0 * DD + c * 4);
        float4 x1 = *(const float4*)(g_cur + (size_t)c1 * DD + c * 4);
        acc.x += p0.y * x0.x + p1.y * x1.x;
        acc.y += p0.y * x0.y + p1.y * x1.y;
        acc.z += p0.y * x0.z + p1.y * x1.z;
        acc.w += p0.y * x0.w + p1.y * x1.w;
    }
    if (i < e) {
        float2 p0 = __ldg(&g_epayG[i]);
        int c0 = __float_as_int(p0.x);
        float4 x0 = *(const float4*)(g_cur + (size_t)c0 * DD + c * 4);
        acc.x += p0.y * x0.x; acc.y += p0.y * x0.y;
        acc.z += p0.y * x0.z; acc.w += p0.y * x0.w;
    }
    *(float4*)(g_gnn + (size_t)r * DD + c * 4) = acc;
}

// ---------------- DCCF: intent — f32x2 row-pair ----------------
#define INTENT_SMEM 82944
#define IT_THREADS 256
#define IT_ROWS_PER_BLOCK 64

__global__ void __launch_bounds__(IT_THREADS) k_intent(const float* __restrict__ Wu,
                                                       const float* __restrict__ Wi) {
    extern __shared__ float sm[];
    float2* WTpw = (float2*)sm;
    const float2* WTp = (const float2*)sm;
    const int tid = threadIdx.x, w = tid >> 5, lane = tid & 31;

    ull* uT2 = (ull*)(sm + 8448) + w * 256;
    ull* pT2 = (ull*)(sm + 12544) + w * 512;

    const int UB = (NU + IT_ROWS_PER_BLOCK - 1) / IT_ROWS_PER_BLOCK;
    const bool isUser = (int)blockIdx.x < UB;
    const float* Wg = isUser ? Wu : Wi;
    const int rowbase = isUser ? (int)blockIdx.x * IT_ROWS_PER_BLOCK
                               : NU + ((int)blockIdx.x - UB) * IT_ROWS_PER_BLOCK;
    const int rowlim = isUser ? NU : NN;

    for (int t = tid; t < 4096; t += IT_THREADS) {
        int L = t >> 7, j = t & 127;
        WTpw[j * 33 + L] = make_float2(Wg[(2 * L) * 128 + j], Wg[(2 * L + 1) * 128 + j]);
    }
    __syncthreads();

    const int r0 = rowbase + w * 8;

    for (int t = lane; t < 256; t += 32) {
        int rho = t >> 6, k = t & 63;
        int ra = r0 + 2 * rho, rb = ra + 1;
        float xa = (ra < rowlim) ? g_cur[(size_t)ra * DD + k] : 0.f;
        float xb = (rb < rowlim) ? g_cur[(size_t)rb * DD + k] : 0.f;
        uT2[rho * 64 + k] = pack2(xa, xb);
    }
    __syncwarp();

    ull acc[4][4];
#pragma unroll
    for (int a = 0; a < 4; a++) { acc[a][0] = acc[a][1] = acc[a][2] = acc[a][3] = 0ull; }

    const ulonglong2* uT2v = (const ulonglong2*)uT2;
#pragma unroll 4
    for (int L = 0; L < 32; L++) {
        float2 w0 = WTp[(lane +  0) * 33 + L];
        float2 w1 = WTp[(lane + 32) * 33 + L];
        float2 w2 = WTp[(lane + 64) * 33 + L];
        float2 w3 = WTp[(lane + 96) * 33 + L];
        ull s0x = pk2(w0.x), s0y = pk2(w0.y);
        ull s1x = pk2(w1.x), s1y = pk2(w1.y);
        ull s2x = pk2(w2.x), s2y = pk2(w2.y);
        ull s3x = pk2(w3.x), s3y = pk2(w3.y);
#pragma unroll
        for (int rho = 0; rho < 4; rho++) {
            ulonglong2 up = uT2v[rho * 32 + L];
            fma2(acc[rho][0], s0x, up.x); fma2(acc[rho][0], s0y, up.y);
            fma2(acc[rho][1], s1x, up.x); fma2(acc[rho][1], s1y, up.y);
            fma2(acc[rho][2], s2x, up.x); fma2(acc[rho][2], s2y, up.y);
            fma2(acc[rho][3], s3x, up.x); fma2(acc[rho][3], s3y, up.y);
        }
    }

#pragma unroll
    for (int rho = 0; rho < 4; rho++) {
        float2 a0 = up2(acc[rho][0]), a1 = up2(acc[rho][1]);
        float2 a2 = up2(acc[rho][2]), a3 = up2(acc[rho][3]);
        float ml = fmaxf(fmaxf(a0.x, a1.x), fmaxf(a2.x, a3.x));
        float mh = fmaxf(fmaxf(a0.y, a1.y), fmaxf(a2.y, a3.y));
#pragma unroll
        for (int off = 16; off; off >>= 1) {
            ml = fmaxf(ml, __shfl_xor_sync(0xffffffffu, ml, off));
            mh = fmaxf(mh, __shfl_xor_sync(0xffffffffu, mh, off));
        }
        float el0 = __expf(a0.x - ml), el1 = __expf(a1.x - ml);
        float el2 = __expf(a2.x - ml), el3 = __expf(a3.x - ml);
        float eh0 = __expf(a0.y - mh), eh1 = __expf(a1.y - mh);
        float eh2 = __expf(a2.y - mh), eh3 = __expf(a3.y - mh);
        float sl = el0 + el1 + el2 + el3;
        float sh = eh0 + eh1 + eh2 + eh3;
#pragma unroll
        for (int off = 16; off; off >>= 1) {
            sl += __shfl_xor_sync(0xffffffffu, sl, off);
            sh += __shfl_xor_sync(0xffffffffu, sh, off);
        }
        float il = 1.f / sl, ih = 1.f / sh;
        pT2[rho * 128 + lane +  0] = pack2(el0 * il, eh0 * ih);
        pT2[rho * 128 + lane + 32] = pack2(el1 * il, eh1 * ih);
        pT2[rho * 128 + lane + 64] = pack2(el2 * il, eh2 * ih);
        pT2[rho * 128 + lane + 96] = pack2(el3 * il, eh3 * ih);
    }
    __syncwarp();

    ull acc2[4][2];
#pragma unroll
    for (int a = 0; a < 4; a++) { acc2[a][0] = 0ull; acc2[a][1] = 0ull; }

    const ulonglong2* pT2v = (const ulonglong2*)pT2;
#pragma unroll 2
    for (int j4 = 0; j4 < 32; j4++) {
        ulonglong2 P0a = pT2v[0 * 64 + 2 * j4], P0b = pT2v[0 * 64 + 2 * j4 + 1];
        ulonglong2 P1a = pT2v[1 * 64 + 2 * j4], P1b = pT2v[1 * 64 + 2 * j4 + 1];
        ulonglong2 P2a = pT2v[2 * 64 + 2 * j4], P2b = pT2v[2 * 64 + 2 * j4 + 1];
        ulonglong2 P3a = pT2v[3 * 64 + 2 * j4], P3b = pT2v[3 * 64 + 2 * j4 + 1];
#define P2J(JJ, PW)                                             \
        {                                                       \
            float2 wt = WTp[(4 * j4 + JJ) * 33 + lane];         \
            ull s0 = pk2(wt.x), s1 = pk2(wt.y);                 \
            fma2(acc2[0][0], s0, P0##PW); fma2(acc2[0][1], s1, P0##PW); \
            fma2(acc2[1][0], s0, P1##PW); fma2(acc2[1][1], s1, P1##PW); \
            fma2(acc2[2][0], s0, P2##PW); fma2(acc2[2][1], s1, P2##PW); \
            fma2(acc2[3][0], s0, P3##PW); fma2(acc2[3][1], s1, P3##PW); \
        }
        P2J(0, a.x) P2J(1, a.y) P2J(2, b.x) P2J(3, b.y)
#undef P2J
    }

#pragma unroll
    for (int rho = 0; rho < 4; rho++) {
        float2 o0 = up2(acc2[rho][0]);
        float2 o1 = up2(acc2[rho][1]);
#pragma unroll
        for (int par = 0; par < 2; par++) {
            int r = r0 + 2 * rho + par;
            if (r >= rowlim) continue;
            float oa = par ? o0.y : o0.x;
            float ob = par ? o1.y : o1.x;
            size_t base = (size_t)r * DD + lane * 2;
            float2 cu = *(const float2*)(g_cur + base);
            float2 gn = *(const float2*)(g_gnn + base);
            float2 tt = *(const float2*)(g_total + base);
            float n0 = gn.x + oa + cu.x;
            float n1 = gn.y + ob + cu.y;
            *(float2*)(g_cur + base) = make_float2(n0, n1);
            *(float2*)(g_total + base) = make_float2(tt.x + n0, tt.y + n1);
        }
    }
}

// ---------------- HAN: CSR gather ----------------
__global__ void __launch_bounds__(256) k_hgather(const float* __restrict__ feat, int E2,
                                                 int n, int base, int rbase, int paybase,
                                                 int zbase) {
    unsigned t = blockIdx.x * 256u + threadIdx.x;
    unsigned idx = t >> 4;
    unsigned c = t & 15u;
    if (idx >= 2u * (unsigned)n) return;
    int m = (idx >= (unsigned)n) ? 1 : 0;
    int node = (int)idx - m * n;
    const int* rptr = g_rptrH + rbase + m * (n + 1);
    int s = rptr[node], e = rptr[node + 1];
    const int* pay = g_hpay + paybase + m * E2;
    const int* dout = g_dout + base + m * n;
    float4 acc = make_float4(0.f, 0.f, 0.f, 0.f);
    int i = s;
    for (; i + 2 <= e; i += 2) {
        int s0 = __ldg(pay + i), s1 = __ldg(pay + i + 1);
        float w0 = rsqrtf((float)__ldg(dout + s0));
        float w1 = rsqrtf((float)__ldg(dout + s1));
        float4 x0 = *(const float4*)(feat + (size_t)s0 * DD + c * 4);
        float4 x1 = *(const float4*)(feat + (size_t)s1 * DD + c * 4);
        acc.x += w0 * x0.x + w1 * x1.x;
        acc.y += w0 * x0.y + w1 * x1.y;
        acc.z += w0 * x0.z + w1 * x1.z;
        acc.w += w0 * x0.w + w1 * x1.w;
    }
    if (i < e) {
        int s0 = __ldg(pay + i);
        float w0 = rsqrtf((float)__ldg(dout + s0));
        float4 x0 = *(const float4*)(feat + (size_t)s0 * DD + c * 4);
        acc.x += w0 * x0.x; acc.y += w0 * x0.y;
        acc.z += w0 * x0.z; acc.w += w0 * x0.w;
    }
    float din = (float)(e - s);
    float sc = (din > 0.f) ? rsqrtf(din) : 0.f;
    *(float4*)(g_z + (size_t)zbase + ((size_t)node * 2 + m) * DD + c * 4) =
        make_float4(acc.x * sc, acc.y * sc, acc.z * sc, acc.w * sc);
}

// ---------------- HAN: semantic attention logits ----------------
__global__ void __launch_bounds__(256) k_han_node(const float* __restrict__ W1g,
                                                  const float* __restrict__ b1g,
                                                  const float* __restrict__ w2g,
                                                  int n, int zbase, int wbase) {
    __shared__ float Wsm[8192];
    __shared__ float ush[4096];
    __shared__ float bsh[128];
    __shared__ float w2sh[128];
    __shared__ float wacc[2];

    const int tid = threadIdx.x, w = tid >> 5, lane = tid & 31;
    for (int t = tid; t < 2048; t += 256) {
        int k = t >> 5, L = t & 31;
        ((float4*)Wsm)[t] = *(const float4*)(W1g + k * 128 + L * 4);
    }
    if (tid < 128) { bsh[tid] = b1g[tid]; w2sh[tid] = w2g[tid]; }
    if (tid < 2) wacc[tid] = 0.f;
    __syncthreads();

    const int rows = 2 * n;
    const int r0 = (int)blockIdx.x * 64 + w * 8;
    float* u = ush + w * 512;

    for (int t = lane; t < 512; t += 32) {
        int rr = t >> 6, d = t & 63;
        int row = r0 + rr;
        u[t] = (row < rows) ? g_z[(size_t)zbase + (size_t)row * DD + d] : 0.f;
    }
    __syncwarp();

    float acc[8][4];
#pragma unroll
    for (int a = 0; a < 8; a++) { acc[a][0] = acc[a][1] = acc[a][2] = acc[a][3] = 0.f; }

#pragma unroll 2
    for (int kk = 0; kk < 16; kk++) {
        float4 w0 = ((const float4*)Wsm)[(4 * kk + 0) * 32 + lane];
        float4 w1 = ((const float4*)Wsm)[(4 * kk + 1) * 32 + lane];
        float4 w2 = ((const float4*)Wsm)[(4 * kk + 2) * 32 + lane];
        float4 w3 = ((const float4*)Wsm)[(4 * kk + 3) * 32 + lane];
#pragma unroll
        for (int rr = 0; rr < 8; rr++) {
            float4 uv = *(const float4*)(u + rr * 64 + kk * 4);
            acc[rr][0] += uv.x * w0.x + uv.y * w1.x + uv.z * w2.x + uv.w * w3.x;
            acc[rr][1] += uv.x * w0.y + uv.y * w1.y + uv.z * w2.y + uv.w * w3.y;
            acc[rr][2] += uv.x * w0.z + uv.y * w1.z + uv.z * w2.z + uv.w * w3.z;
            acc[rr][3] += uv.x * w0.w + uv.y * w1.w + uv.z * w2.w + uv.w * w3.w;
        }
    }

    float wl01[2] = {0.f, 0.f};
#pragma unroll
    for (int rr = 0; rr < 8; rr++) {
        int row = r0 + rr;
        float wl = 0.f;
#pragma unroll
        for (int c = 0; c < 4; c++) {
            int j = lane * 4 + c;
            wl += tanhf(acc[rr][c] + bsh[j]) * w2sh[j];
        }
        if (row < rows) wl01[row & 1] += wl;
    }
#pragma unroll
    for (int off = 16; off; off >>= 1) {
        wl01[0] += __shfl_xor_sync(0xffffffffu, wl01[0], off);
        wl01[1] += __shfl_xor_sync(0xffffffffu, wl01[1], off);
    }
    if (lane == 0) {
        atomicAdd(&wacc[0], wl01[0]);
        atomicAdd(&wacc[1], wl01[1]);
    }
    __syncthreads();
    if (tid < 2) atomicAdd(&g_wsum[wbase + tid], wacc[tid]);
}

// ---------------- final combine ----------------
__global__ void __launch_bounds__(256) k_combine(float* __restrict__ out) {
    unsigned i = blockIdx.x * 256u + threadIdx.x;
    if (i >= (unsigned)(NN * DD)) return;
    unsigned node = i >> 6, d = i & 63u;
    float w0, w1;
    size_t zr;
    if (node < NU) {
        w0 = g_wsum[0] * (1.f / NU);
        w1 = g_wsum[1] * (1.f / NU);
        zr = (size_t)node * 128;
    } else {
        w0 = g_wsum[2] * (1.f / NI);
        w1 = g_wsum[3] * (1.f / NI);
        zr = (size_t)NU * 128 + (size_t)(node - NU) * 128;
    }
    float mx = fmaxf(w0, w1);
    float e0 = __expf(w0 - mx), e1 = __expf(w1 - mx);
    float inv = 1.f / (e0 + e1);
    float han = (e0 * inv) * g_z[zr + d] + (e1 * inv) * g_z[zr + 64 + d];
    out[i] = 0.5f * g_total[i] + 0.5f * han;
}

// ---------------- launcher: 3 streams ----------------
extern "C" void kernel_launch(void* const* d_in, const int* in_sizes, int n_in,
                              void* d_out, int out_size) {
    const int*   G    = (const int*)d_in[0];
    const float* Gv   = (const float*)d_in[1];
    const float* fu   = (const float*)d_in[2];
    const float* fi   = (const float*)d_in[3];
    const float* Wu   = (const float*)d_in[4];
    const float* Wi   = (const float*)d_in[5];
    const int*   eu   = (const int*)d_in[6];
    const int*   ei   = (const int*)d_in[7];
    const float* suW1 = (const float*)d_in[8];
    const float* sub1 = (const float*)d_in[9];
    const float* suw2 = (const float*)d_in[10];
    const float* siW1 = (const float*)d_in[11];
    const float* sib1 = (const float*)d_in[12];
    const float* siw2 = (const float*)d_in[13];
    float* out = (float*)d_out;

    static cudaStream_t s_han = nullptr, s_init = nullptr;
    static cudaEvent_t ev_fork = nullptr, ev_join = nullptr, ev_init = nullptr;
    if (!s_han) {
        cudaStreamCreateWithFlags(&s_han, cudaStreamNonBlocking);
        cudaStreamCreateWithFlags(&s_init, cudaStreamNonBlocking);
        cudaEventCreateWithFlags(&ev_fork, cudaEventDisableTiming);
        cudaEventCreateWithFlags(&ev_join, cudaEventDisableTiming);
        cudaEventCreateWithFlags(&ev_init, cudaEventDisableTiming);
        cudaFuncSetAttribute(k_intent, cudaFuncAttributeMaxDynamicSharedMemorySize,
                             INTENT_SMEM);
    }

    const int UB = (NU + IT_ROWS_PER_BLOCK - 1) / IT_ROWS_PER_BLOCK;
    const int IB = (NI + IT_ROWS_PER_BLOCK - 1) / IT_ROWS_PER_BLOCK;

    // common prologue on main stream
    k_zero_cnt<<<1172, 256>>>();
    cudaEventRecord(ev_fork, 0);

    // ---- init on its own stream (independent of counters) ----
    cudaStreamWaitEvent(s_init, ev_fork, 0);
    k_init<<<37500, 256, 0, s_init>>>(fu, fi);
    cudaEventRecord(ev_init, s_init);

    // ---- HAN chain on side stream ----
    cudaStreamWaitEvent(s_han, ev_fork, 0);
    k_histH<<<12500, 256, 0, s_han>>>(eu, EU_, NU, 0);
    k_histH<<<6250, 256, 0, s_han>>>(ei, EI_, NI, 2 * NU);
    k_scanH1<<<2 * NB_HU + 2 * NB_HI, 1024, 0, s_han>>>();
    k_scanH2<<<1, 128, 0, s_han>>>();
    k_scanH3<<<2 * NB_HU + 2 * NB_HI, 1024, 0, s_han>>>();
    k_fillH<<<12500, 256, 0, s_han>>>(eu, EU_, NU, 0, 0, 0);
    k_fillH<<<6250, 256, 0, s_han>>>(ei, EI_, NI, 2 * NU, 2 * (NU + 1), 2 * EU_);
    k_hgather<<<12500, 256, 0, s_han>>>(fu, EU_, NU, 0, 0, 0, 0);
    k_hgather<<<6250, 256, 0, s_han>>>(fi, EI_, NI, 2 * NU, 2 * (NU + 1), 2 * EU_, NU * 128);
    k_han_node<<<3125, 256, 0, s_han>>>(suW1, sub1, suw2, NU, 0, 0);
    k_han_node<<<1563, 256, 0, s_han>>>(siW1, sib1, siw2, NI, NU * 128, 2);
    cudaEventRecord(ev_join, s_han);

    // ---- DCCF chain on main stream ----
    k_histG<<<12500, 256>>>(G);
    k_scanG1<<<NB_G, 1024>>>();
    k_scanG2<<<1, 32>>>();
    k_scanG3<<<NB_G, 1024>>>();
    k_fillG<<<12500, 256>>>(G, Gv);
    cudaStreamWaitEvent(0, ev_init, 0);
    for (int layer = 0; layer < 2; layer++) {
        k_spmm_csr<<<9375, 256>>>();
        k_intent<<<UB + IB, IT_THREADS, INTENT_SMEM>>>(Wu, Wi);
    }

    // ---- join + combine ----
    cudaStreamWaitEvent(0, ev_join, 0);
    k_combine<<<37500, 256>>>(out);
}

// round 11
// speedup vs baseline: 1.4934x; 1.0151x over previous
#include <cuda_runtime.h>

#define NU 100000
#define NI 50000
#define NN 150000
#define DD 64
#define EG 3200000
#define EU_ 1600000
#define EI_ 800000

typedef unsigned long long ull;

// ---------------- device scratch ----------------
__device__ float g_cur[NN * DD];
__device__ float g_gnn[NN * DD];
__device__ float g_int[NN * DD];
__device__ float g_total[NN * DD];
__device__ float g_z[NN * 2 * DD];
__device__ float g_wsum[4];

// CSR for G
__device__ int    g_cntG[NN];
__device__ int    g_curG[NN];
__device__ int    g_rptrG[NN + 1];
__device__ float2 g_epayG[EG];

// CSR + degrees for HAN
#define HN (2 * NU + 2 * NI)
__device__ int g_dout[HN];
__device__ int g_din[HN];
__device__ int g_curH[HN];
__device__ int g_rptrH[2 * (NU + 1) + 2 * (NI + 1)];
__device__ int g_hpay[2 * EU_ + 2 * EI_];

// block-sum scratch for parallel scans
#define NB_G 147
#define NB_HU 98
#define NB_HI 49
__device__ int g_bsumG[NB_G];
__device__ int g_bsumH[4 * NB_HU];

// f32x2 packed math (sm_100+)
__device__ __forceinline__ ull pk2(float a) {
    ull r;
    asm("mov.b64 %0, {%1, %1};" : "=l"(r) : "f"(a));
    return r;
}
__device__ __forceinline__ ull pack2(float lo, float hi) {
    ull r;
    asm("mov.b64 %0, {%1, %2};" : "=l"(r) : "f"(lo), "f"(hi));
    return r;
}
__device__ __forceinline__ void fma2(ull& d, ull a, ull b) {
    asm("fma.rn.f32x2 %0, %1, %2, %0;" : "+l"(d) : "l"(a), "l"(b));
}
__device__ __forceinline__ float2 up2(ull v) {
    float2 f;
    asm("mov.b64 {%0, %1}, %2;" : "=f"(f.x), "=f"(f.y) : "l"(v));
    return f;
}

// ---------------- zero counters ----------------
__global__ void __launch_bounds__(256) k_zero_cnt() {
    unsigned i = blockIdx.x * 256u + threadIdx.x;
    if (i < NN) { g_cntG[i] = 0; g_curG[i] = 0; }
    if (i < HN) { g_dout[i] = 0; g_din[i] = 0; g_curH[i] = 0; }
    if (i < 4u) g_wsum[i] = 0.f;
}

// ---------------- init ----------------
__global__ void __launch_bounds__(256) k_init(const float* __restrict__ fu,
                                              const float* __restrict__ fi) {
    unsigned i = blockIdx.x * 256u + threadIdx.x;
    if (i < NU * DD) {
        float v = fu[i];
        g_cur[i] = v; g_total[i] = v;
    } else if (i < NN * DD) {
        float v = fi[i - NU * DD];
        g_cur[i] = v; g_total[i] = v;
    }
}

// ---------------- histograms ----------------
__global__ void __launch_bounds__(256) k_histG(const int* __restrict__ G) {
    unsigned e = blockIdx.x * 256u + threadIdx.x;
    if (e >= EG) return;
    atomicAdd(&g_cntG[__ldg(G + e)], 1);
}

__global__ void __launch_bounds__(256) k_histH(const int* __restrict__ edges, int E2,
                                               int n, int base) {
    unsigned t = blockIdx.x * 256u + threadIdx.x;
    if (t >= 2u * (unsigned)E2) return;
    int m = (t >= (unsigned)E2) ? 1 : 0;
    int e = (int)t - m * E2;
    int src = __ldg(edges + (size_t)m * 2 * E2 + e);
    int dst = __ldg(edges + (size_t)m * 2 * E2 + E2 + e);
    atomicAdd(&g_dout[base + m * n + src], 1);
    atomicAdd(&g_din[base + m * n + dst], 1);
}

// ---------------- parallel scans ----------------
__device__ __forceinline__ int blockscan_1024(int v, int* ws) {
    const int tid = threadIdx.x, lane = tid & 31, wid = tid >> 5;
    int x = v;
#pragma unroll
    for (int off = 1; off < 32; off <<= 1) {
        int y = __shfl_up_sync(0xffffffffu, x, off);
        if (lane >= off) x += y;
    }
    if (lane == 31) ws[wid] = x;
    __syncthreads();
    if (wid == 0) {
        int s = ws[lane];
#pragma unroll
        for (int off = 1; off < 32; off <<= 1) {
            int y = __shfl_up_sync(0xffffffffu, s, off);
            if (lane >= off) s += y;
        }
        ws[lane] = s;
    }
    __syncthreads();
    return x - v + (wid > 0 ? ws[wid - 1] : 0);
}

__global__ void __launch_bounds__(1024) k_scanG1() {
    __shared__ int ws[32];
    int i = blockIdx.x * 1024 + threadIdx.x;
    int v = (i < NN) ? g_cntG[i] : 0;
    int excl = blockscan_1024(v, ws);
    if (i < NN) g_rptrG[i] = excl;
    if (threadIdx.x == 0) g_bsumG[blockIdx.x] = ws[31];
}

__global__ void __launch_bounds__(32) k_scanG2() {
    int lane = threadIdx.x;
    int carry = 0;
    for (int base = 0; base < NB_G; base += 32) {
        int idx = base + lane;
        int v = (idx < NB_G) ? g_bsumG[idx] : 0;
        int x = v;
#pragma unroll
        for (int off = 1; off < 32; off <<= 1) {
            int y = __shfl_up_sync(0xffffffffu, x, off);
            if (lane >= off) x += y;
        }
        if (idx < NB_G) g_bsumG[idx] = x - v + carry;
        carry += __shfl_sync(0xffffffffu, x, 31);
    }
    if (lane == 0) g_rptrG[NN] = carry;
}

__global__ void __launch_bounds__(1024) k_scanG3() {
    int i = blockIdx.x * 1024 + threadIdx.x;
    if (i < NN) g_rptrG[i] += g_bsumG[blockIdx.x];
}

__device__ __forceinline__ void hseg_decode(int b, int& seg, int& lb, int& n,
                                            const int*& cnt, int*& rptr) {
    if (b < NB_HU)           { seg = 0; lb = b; }
    else if (b < 2 * NB_HU)  { seg = 1; lb = b - NB_HU; }
    else if (b < 2 * NB_HU + NB_HI) { seg = 2; lb = b - 2 * NB_HU; }
    else                     { seg = 3; lb = b - 2 * NB_HU - NB_HI; }
    n = (seg < 2) ? NU : NI;
    cnt = g_din + (seg == 0 ? 0 : seg == 1 ? NU : seg == 2 ? 2 * NU : 2 * NU + NI);
    rptr = g_rptrH + (seg == 0 ? 0 : seg == 1 ? (NU + 1)
                      : seg == 2 ? 2 * (NU + 1) : 2 * (NU + 1) + (NI + 1));
}

__global__ void __launch_bounds__(1024) k_scanH1() {
    __shared__ int ws[32];
    int seg, lb, n; const int* cnt; int* rptr;
    hseg_decode(blockIdx.x, seg, lb, n, cnt, rptr);
    int i = lb * 1024 + threadIdx.x;
    int v = (i < n) ? cnt[i] : 0;
    int excl = blockscan_1024(v, ws);
    if (i < n) rptr[i] = excl;
    if (threadIdx.x == 0) g_bsumH[seg * NB_HU + lb] = ws[31];
}

__global__ void __launch_bounds__(128) k_scanH2() {
    int lane = threadIdx.x & 31, seg = threadIdx.x >> 5;
    int nb = (seg < 2) ? NB_HU : NB_HI;
    int n = (seg < 2) ? NU : NI;
    int* rptr = g_rptrH + (seg == 0 ? 0 : seg == 1 ? (NU + 1)
                           : seg == 2 ? 2 * (NU + 1) : 2 * (NU + 1) + (NI + 1));
    int* bs = g_bsumH + seg * NB_HU;
    int carry = 0;
    for (int base = 0; base < nb; base += 32) {
        int idx = base + lane;
        int v = (idx < nb) ? bs[idx] : 0;
        int x = v;
#pragma unroll
        for (int off = 1; off < 32; off <<= 1) {
            int y = __shfl_up_sync(0xffffffffu, x, off);
            if (lane >= off) x += y;
        }
        if (idx < nb) bs[idx] = x - v + carry;
        carry += __shfl_sync(0xffffffffu, x, 31);
    }
    if (lane == 0) rptr[n] = carry;
}

__global__ void __launch_bounds__(1024) k_scanH3() {
    int seg, lb, n; const int* cnt; int* rptr;
    hseg_decode(blockIdx.x, seg, lb, n, cnt, rptr);
    int i = lb * 1024 + threadIdx.x;
    if (i < n) rptr[i] += g_bsumH[seg * NB_HU + lb];
}

// ---------------- CSR fill ----------------
__global__ void __launch_bounds__(256) k_fillG(const int* __restrict__ G,
                                               const float* __restrict__ gv) {
    unsigned e = blockIdx.x * 256u + threadIdx.x;
    if (e >= EG) return;
    int row = __ldg(G + e);
    int col = __ldg(G + EG + e);
    float v = __ldg(gv + e);
    int pos = g_rptrG[row] + atomicAdd(&g_curG[row], 1);
    g_epayG[pos] = make_float2(__int_as_float(col), v);
}

__global__ void __launch_bounds__(256) k_fillH(const int* __restrict__ edges, int E2,
                                               int n, int base, int rbase, int paybase) {
    unsigned t = blockIdx.x * 256u + threadIdx.x;
    if (t >= 2u * (unsigned)E2) return;
    int m = (t >= (unsigned)E2) ? 1 : 0;
    int e = (int)t - m * E2;
    int src = __ldg(edges + (size_t)m * 2 * E2 + e);
    int dst = __ldg(edges + (size_t)m * 2 * E2 + E2 + e);
    const int* rptr = g_rptrH + rbase + m * (n + 1);
    int pos = rptr[dst] + atomicAdd(&g_curH[base + m * n + dst], 1);
    g_hpay[paybase + m * E2 + pos] = src;
}

// ---------------- DCCF: CSR SpMM ----------------
__global__ void __launch_bounds__(256) k_spmm_csr() {
    unsigned t = blockIdx.x * 256u + threadIdx.x;
    unsigned r = t >> 4;
    unsigned c = t & 15u;
    if (r >= NN) return;
    int s = g_rptrG[r], e = g_rptrG[r + 1];
    float4 acc = make_float4(0.f, 0.f, 0.f, 0.f);
    int i = s;
    for (; i + 2 <= e; i += 2) {
        float2 p0 = __ldg(&g_epayG[i]);
        float2 p1 = __ldg(&g_epayG[i + 1]);
        int c0 = __float_as_int(p0.x), c1 = __float_as_int(p1.x);
        float4 x0 = *(const float4*)(g_cur + (size_t)c0 * DD + c * 4);
        float4 x1 = *(const float4*)(g_cur + (size_t)c1 * DD + c * 4);
        acc.x += p0.y * x0.x + p1.y * x1.x;
        acc.y += p0.y * x0.y + p1.y * x1.y;
        acc.z += p0.y * x0.z + p1.y * x1.z;
        acc.w += p0.y * x0.w + p1.y * x1.w;
    }
    if (i < e) {
        float2 p0 = __ldg(&g_epayG[i]);
        int c0 = __float_as_int(p0.x);
        float4 x0 = *(const float4*)(g_cur + (size_t)c0 * DD + c * 4);
        acc.x += p0.y * x0.x; acc.y += p0.y * x0.y;
        acc.z += p0.y * x0.z; acc.w += p0.y * x0.w;
    }
    *(float4*)(g_gnn + (size_t)r * DD + c * 4) = acc;
}

// ---------------- DCCF: intent projection (writes g_int only) ----------------
#define INTENT_SMEM 82944
#define IT_THREADS 256
#define IT_ROWS_PER_BLOCK 64

__global__ void __launch_bounds__(IT_THREADS) k_intent(const float* __restrict__ Wu,
                                                       const float* __restrict__ Wi) {
    extern __shared__ float sm[];
    float2* WTpw = (float2*)sm;
    const float2* WTp = (const float2*)sm;
    const int tid = threadIdx.x, w = tid >> 5, lane = tid & 31;

    ull* uT2 = (ull*)(sm + 8448) + w * 256;
    ull* pT2 = (ull*)(sm + 12544) + w * 512;

    const int UB = (NU + IT_ROWS_PER_BLOCK - 1) / IT_ROWS_PER_BLOCK;
    const bool isUser = (int)blockIdx.x < UB;
    const float* Wg = isUser ? Wu : Wi;
    const int rowbase = isUser ? (int)blockIdx.x * IT_ROWS_PER_BLOCK
                               : NU + ((int)blockIdx.x - UB) * IT_ROWS_PER_BLOCK;
    const int rowlim = isUser ? NU : NN;

    for (int t = tid; t < 4096; t += IT_THREADS) {
        int L = t >> 7, j = t & 127;
        WTpw[j * 33 + L] = make_float2(Wg[(2 * L) * 128 + j], Wg[(2 * L + 1) * 128 + j]);
    }
    __syncthreads();

    const int r0 = rowbase + w * 8;

    for (int t = lane; t < 256; t += 32) {
        int rho = t >> 6, k = t & 63;
        int ra = r0 + 2 * rho, rb = ra + 1;
        float xa = (ra < rowlim) ? g_cur[(size_t)ra * DD + k] : 0.f;
        float xb = (rb < rowlim) ? g_cur[(size_t)rb * DD + k] : 0.f;
        uT2[rho * 64 + k] = pack2(xa, xb);
    }
    __syncwarp();

    ull acc[4][4];
#pragma unroll
    for (int a = 0; a < 4; a++) { acc[a][0] = acc[a][1] = acc[a][2] = acc[a][3] = 0ull; }

    const ulonglong2* uT2v = (const ulonglong2*)uT2;
#pragma unroll 4
    for (int L = 0; L < 32; L++) {
        float2 w0 = WTp[(lane +  0) * 33 + L];
        float2 w1 = WTp[(lane + 32) * 33 + L];
        float2 w2 = WTp[(lane + 64) * 33 + L];
        float2 w3 = WTp[(lane + 96) * 33 + L];
        ull s0x = pk2(w0.x), s0y = pk2(w0.y);
        ull s1x = pk2(w1.x), s1y = pk2(w1.y);
        ull s2x = pk2(w2.x), s2y = pk2(w2.y);
        ull s3x = pk2(w3.x), s3y = pk2(w3.y);
#pragma unroll
        for (int rho = 0; rho < 4; rho++) {
            ulonglong2 up = uT2v[rho * 32 + L];
            fma2(acc[rho][0], s0x, up.x); fma2(acc[rho][0], s0y, up.y);
            fma2(acc[rho][1], s1x, up.x); fma2(acc[rho][1], s1y, up.y);
            fma2(acc[rho][2], s2x, up.x); fma2(acc[rho][2], s2y, up.y);
            fma2(acc[rho][3], s3x, up.x); fma2(acc[rho][3], s3y, up.y);
        }
    }

#pragma unroll
    for (int rho = 0; rho < 4; rho++) {
        float2 a0 = up2(acc[rho][0]), a1 = up2(acc[rho][1]);
        float2 a2 = up2(acc[rho][2]), a3 = up2(acc[rho][3]);
        float ml = fmaxf(fmaxf(a0.x, a1.x), fmaxf(a2.x, a3.x));
        float mh = fmaxf(fmaxf(a0.y, a1.y), fmaxf(a2.y, a3.y));
#pragma unroll
        for (int off = 16; off; off >>= 1) {
            ml = fmaxf(ml, __shfl_xor_sync(0xffffffffu, ml, off));
            mh = fmaxf(mh, __shfl_xor_sync(0xffffffffu, mh, off));
        }
        float el0 = __expf(a0.x - ml), el1 = __expf(a1.x - ml);
        float el2 = __expf(a2.x - ml), el3 = __expf(a3.x - ml);
        float eh0 = __expf(a0.y - mh), eh1 = __expf(a1.y - mh);
        float eh2 = __expf(a2.y - mh), eh3 = __expf(a3.y - mh);
        float sl = el0 + el1 + el2 + el3;
        float sh = eh0 + eh1 + eh2 + eh3;
#pragma unroll
        for (int off = 16; off; off >>= 1) {
            sl += __shfl_xor_sync(0xffffffffu, sl, off);
            sh += __shfl_xor_sync(0xffffffffu, sh, off);
        }
        float il = 1.f / sl, ih = 1.f / sh;
        pT2[rho * 128 + lane +  0] = pack2(el0 * il, eh0 * ih);
        pT2[rho * 128 + lane + 32] = pack2(el1 * il, eh1 * ih);
        pT2[rho * 128 + lane + 64] = pack2(el2 * il, eh2 * ih);
        pT2[rho * 128 + lane + 96] = pack2(el3 * il, eh3 * ih);
    }
    __syncwarp();

    ull acc2[4][2];
#pragma unroll
    for (int a = 0; a < 4; a++) { acc2[a][0] = 0ull; acc2[a][1] = 0ull; }

    const ulonglong2* pT2v = (const ulonglong2*)pT2;
#pragma unroll 2
    for (int j4 = 0; j4 < 32; j4++) {
        ulonglong2 P0a = pT2v[0 * 64 + 2 * j4], P0b = pT2v[0 * 64 + 2 * j4 + 1];
        ulonglong2 P1a = pT2v[1 * 64 + 2 * j4], P1b = pT2v[1 * 64 + 2 * j4 + 1];
        ulonglong2 P2a = pT2v[2 * 64 + 2 * j4], P2b = pT2v[2 * 64 + 2 * j4 + 1];
        ulonglong2 P3a = pT2v[3 * 64 + 2 * j4], P3b = pT2v[3 * 64 + 2 * j4 + 1];
#define P2J(JJ, PW)                                             \
        {                                                       \
            float2 wt = WTp[(4 * j4 + JJ) * 33 + lane];         \
            ull s0 = pk2(wt.x), s1 = pk2(wt.y);                 \
            fma2(acc2[0][0], s0, P0##PW); fma2(acc2[0][1], s1, P0##PW); \
            fma2(acc2[1][0], s0, P1##PW); fma2(acc2[1][1], s1, P1##PW); \
            fma2(acc2[2][0], s0, P2##PW); fma2(acc2[2][1], s1, P2##PW); \
            fma2(acc2[3][0], s0, P3##PW); fma2(acc2[3][1], s1, P3##PW); \
        }
        P2J(0, a.x) P2J(1, a.y) P2J(2, b.x) P2J(3, b.y)
#undef P2J
    }

#pragma unroll
    for (int rho = 0; rho < 4; rho++) {
        float2 o0 = up2(acc2[rho][0]);
        float2 o1 = up2(acc2[rho][1]);
#pragma unroll
        for (int par = 0; par < 2; par++) {
            int r = r0 + 2 * rho + par;
            if (r >= rowlim) continue;
            float oa = par ? o0.y : o0.x;
            float ob = par ? o1.y : o1.x;
            *(float2*)(g_int + (size_t)r * DD + lane * 2) = make_float2(oa, ob);
        }
    }
}

// ---------------- DCCF: layer epilogue cur = gnn + int + cur; total += cur ----------------
__global__ void __launch_bounds__(256) k_epi() {
    unsigned i = blockIdx.x * 256u + threadIdx.x;
    if (i >= (unsigned)(NN * DD / 4)) return;
    float4 gn = ((const float4*)g_gnn)[i];
    float4 iv = ((const float4*)g_int)[i];
    float4 cu = ((const float4*)g_cur)[i];
    float4 tt = ((const float4*)g_total)[i];
    float4 nv;
    nv.x = gn.x + iv.x + cu.x;
    nv.y = gn.y + iv.y + cu.y;
    nv.z = gn.z + iv.z + cu.z;
    nv.w = gn.w + iv.w + cu.w;
    ((float4*)g_cur)[i] = nv;
    tt.x += nv.x; tt.y += nv.y; tt.z += nv.z; tt.w += nv.w;
    ((float4*)g_total)[i] = tt;
}

// ---------------- HAN: CSR gather ----------------
__global__ void __launch_bounds__(256) k_hgather(const float* __restrict__ feat, int E2,
                                                 int n, int base, int rbase, int paybase,
                                                 int zbase) {
    unsigned t = blockIdx.x * 256u + threadIdx.x;
    unsigned idx = t >> 4;
    unsigned c = t & 15u;
    if (idx >= 2u * (unsigned)n) return;
    int m = (idx >= (unsigned)n) ? 1 : 0;
    int node = (int)idx - m * n;
    const int* rptr = g_rptrH + rbase + m * (n + 1);
    int s = rptr[node], e = rptr[node + 1];
    const int* pay = g_hpay + paybase + m * E2;
    const int* dout = g_dout + base + m * n;
    float4 acc = make_float4(0.f, 0.f, 0.f, 0.f);
    int i = s;
    for (; i + 2 <= e; i += 2) {
        int s0 = __ldg(pay + i), s1 = __ldg(pay + i + 1);
        float w0 = rsqrtf((float)__ldg(dout + s0));
        float w1 = rsqrtf((float)__ldg(dout + s1));
        float4 x0 = *(const float4*)(feat + (size_t)s0 * DD + c * 4);
        float4 x1 = *(const float4*)(feat + (size_t)s1 * DD + c * 4);
        acc.x += w0 * x0.x + w1 * x1.x;
        acc.y += w0 * x0.y + w1 * x1.y;
        acc.z += w0 * x0.z + w1 * x1.z;
        acc.w += w0 * x0.w + w1 * x1.w;
    }
    if (i < e) {
        int s0 = __ldg(pay + i);
        float w0 = rsqrtf((float)__ldg(dout + s0));
        float4 x0 = *(const float4*)(feat + (size_t)s0 * DD + c * 4);
        acc.x += w0 * x0.x; acc.y += w0 * x0.y;
        acc.z += w0 * x0.z; acc.w += w0 * x0.w;
    }
    float din = (float)(e - s);
    float sc = (din > 0.f) ? rsqrtf(din) : 0.f;
    *(float4*)(g_z + (size_t)zbase + ((size_t)node * 2 + m) * DD + c * 4) =
        make_float4(acc.x * sc, acc.y * sc, acc.z * sc, acc.w * sc);
}

// ---------------- HAN: semantic attention logits ----------------
__global__ void __launch_bounds__(256) k_han_node(const float* __restrict__ W1g,
                                                  const float* __restrict__ b1g,
                                                  const float* __restrict__ w2g,
                                                  int n, int zbase, int wbase) {
    __shared__ float Wsm[8192];
    __shared__ float ush[4096];
    __shared__ float bsh[128];
    __shared__ float w2sh[128];
    __shared__ float wacc[2];

    const int tid = threadIdx.x, w = tid >> 5, lane = tid & 31;
    for (int t = tid; t < 2048; t += 256) {
        int k = t >> 5, L = t & 31;
        ((float4*)Wsm)[t] = *(const float4*)(W1g + k * 128 + L * 4);
    }
    if (tid < 128) { bsh[tid] = b1g[tid]; w2sh[tid] = w2g[tid]; }
    if (tid < 2) wacc[tid] = 0.f;
    __syncthreads();

    const int rows = 2 * n;
    const int r0 = (int)blockIdx.x * 64 + w * 8;
    float* u = ush + w * 512;

    for (int t = lane; t < 512; t += 32) {
        int rr = t >> 6, d = t & 63;
        int row = r0 + rr;
        u[t] = (row < rows) ? g_z[(size_t)zbase + (size_t)row * DD + d] : 0.f;
    }
    __syncwarp();

    float acc[8][4];
#pragma unroll
    for (int a = 0; a < 8; a++) { acc[a][0] = acc[a][1] = acc[a][2] = acc[a][3] = 0.f; }

#pragma unroll 2
    for (int kk = 0; kk < 16; kk++) {
        float4 w0 = ((const float4*)Wsm)[(4 * kk + 0) * 32 + lane];
        float4 w1 = ((const float4*)Wsm)[(4 * kk + 1) * 32 + lane];
        float4 w2 = ((const float4*)Wsm)[(4 * kk + 2) * 32 + lane];
        float4 w3 = ((const float4*)Wsm)[(4 * kk + 3) * 32 + lane];
#pragma unroll
        for (int rr = 0; rr < 8; rr++) {
            float4 uv = *(const float4*)(u + rr * 64 + kk * 4);
            acc[rr][0] += uv.x * w0.x + uv.y * w1.x + uv.z * w2.x + uv.w * w3.x;
            acc[rr][1] += uv.x * w0.y + uv.y * w1.y + uv.z * w2.y + uv.w * w3.y;
            acc[rr][2] += uv.x * w0.z + uv.y * w1.z + uv.z * w2.z + uv.w * w3.z;
            acc[rr][3] += uv.x * w0.w + uv.y * w1.w + uv.z * w2.w + uv.w * w3.w;
        }
    }

    float wl01[2] = {0.f, 0.f};
#pragma unroll
    for (int rr = 0; rr < 8; rr++) {
        int row = r0 + rr;
        float wl = 0.f;
#pragma unroll
        for (int c = 0; c < 4; c++) {
            int j = lane * 4 + c;
            wl += tanhf(acc[rr][c] + bsh[j]) * w2sh[j];
        }
        if (row < rows) wl01[row & 1] += wl;
    }
#pragma unroll
    for (int off = 16; off; off >>= 1) {
        wl01[0] += __shfl_xor_sync(0xffffffffu, wl01[0], off);
        wl01[1] += __shfl_xor_sync(0xffffffffu, wl01[1], off);
    }
    if (lane == 0) {
        atomicAdd(&wacc[0], wl01[0]);
        atomicAdd(&wacc[1], wl01[1]);
    }
    __syncthreads();
    if (tid < 2) atomicAdd(&g_wsum[wbase + tid], wacc[tid]);
}

// ---------------- final combine ----------------
__global__ void __launch_bounds__(256) k_combine(float* __restrict__ out) {
    unsigned i = blockIdx.x * 256u + threadIdx.x;
    if (i >= (unsigned)(NN * DD)) return;
    unsigned node = i >> 6, d = i & 63u;
    float w0, w1;
    size_t zr;
    if (node < NU) {
        w0 = g_wsum[0] * (1.f / NU);
        w1 = g_wsum[1] * (1.f / NU);
        zr = (size_t)node * 128;
    } else {
        w0 = g_wsum[2] * (1.f / NI);
        w1 = g_wsum[3] * (1.f / NI);
        zr = (size_t)NU * 128 + (size_t)(node - NU) * 128;
    }
    float mx = fmaxf(w0, w1);
    float e0 = __expf(w0 - mx), e1 = __expf(w1 - mx);
    float inv = 1.f / (e0 + e1);
    float han = (e0 * inv) * g_z[zr + d] + (e1 * inv) * g_z[zr + 64 + d];
    out[i] = 0.5f * g_total[i] + 0.5f * han;
}

// ---------------- launcher: fork spmm ∥ intent per layer ----------------
extern "C" void kernel_launch(void* const* d_in, const int* in_sizes, int n_in,
                              void* d_out, int out_size) {
    const int*   G    = (const int*)d_in[0];
    const float* Gv   = (const float*)d_in[1];
    const float* fu   = (const float*)d_in[2];
    const float* fi   = (const float*)d_in[3];
    const float* Wu   = (const float*)d_in[4];
    const float* Wi   = (const float*)d_in[5];
    const int*   eu   = (const int*)d_in[6];
    const int*   ei   = (const int*)d_in[7];
    const float* suW1 = (const float*)d_in[8];
    const float* sub1 = (const float*)d_in[9];
    const float* suw2 = (const float*)d_in[10];
    const float* siW1 = (const float*)d_in[11];
    const float* sib1 = (const float*)d_in[12];
    const float* siw2 = (const float*)d_in[13];
    float* out = (float*)d_out;

    static cudaStream_t s_han = nullptr, s_int = nullptr;
    static cudaEvent_t ev_fork = nullptr, ev_join = nullptr, ev_init = nullptr;
    static cudaEvent_t ev_i1 = nullptr, ev_i2 = nullptr, ev_e1 = nullptr;
    if (!s_han) {
        cudaStreamCreateWithFlags(&s_han, cudaStreamNonBlocking);
        cudaStreamCreateWithFlags(&s_int, cudaStreamNonBlocking);
        cudaEventCreateWithFlags(&ev_fork, cudaEventDisableTiming);
        cudaEventCreateWithFlags(&ev_join, cudaEventDisableTiming);
        cudaEventCreateWithFlags(&ev_init, cudaEventDisableTiming);
        cudaEventCreateWithFlags(&ev_i1, cudaEventDisableTiming);
        cudaEventCreateWithFlags(&ev_i2, cudaEventDisableTiming);
        cudaEventCreateWithFlags(&ev_e1, cudaEventDisableTiming);
        cudaFuncSetAttribute(k_intent, cudaFuncAttributeMaxDynamicSharedMemorySize,
                             INTENT_SMEM);
    }

    const int UB = (NU + IT_ROWS_PER_BLOCK - 1) / IT_ROWS_PER_BLOCK;
    const int IB = (NI + IT_ROWS_PER_BLOCK - 1) / IT_ROWS_PER_BLOCK;

    // prologue
    k_zero_cnt<<<1172, 256>>>();
    k_init<<<37500, 256>>>(fu, fi);          // main stream: init before fork
    cudaEventRecord(ev_fork, 0);

    // ---- HAN chain on side stream ----
    cudaStreamWaitEvent(s_han, ev_fork, 0);
    k_histH<<<12500, 256, 0, s_han>>>(eu, EU_, NU, 0);
    k_histH<<<6250, 256, 0, s_han>>>(ei, EI_, NI, 2 * NU);
    k_scanH1<<<2 * NB_HU + 2 * NB_HI, 1024, 0, s_han>>>();
    k_scanH2<<<1, 128, 0, s_han>>>();
    k_scanH3<<<2 * NB_HU + 2 * NB_HI, 1024, 0, s_han>>>();
    k_fillH<<<12500, 256, 0, s_han>>>(eu, EU_, NU, 0, 0, 0);
    k_fillH<<<6250, 256, 0, s_han>>>(ei, EI_, NI, 2 * NU, 2 * (NU + 1), 2 * EU_);
    k_hgather<<<12500, 256, 0, s_han>>>(fu, EU_, NU, 0, 0, 0, 0);
    k_hgather<<<6250, 256, 0, s_han>>>(fi, EI_, NI, 2 * NU, 2 * (NU + 1), 2 * EU_, NU * 128);
    k_han_node<<<3125, 256, 0, s_han>>>(suW1, sub1, suw2, NU, 0, 0);
    k_han_node<<<1563, 256, 0, s_han>>>(siW1, sib1, siw2, NI, NU * 128, 2);
    cudaEventRecord(ev_join, s_han);

    // ---- layer 1 intent on s_int (needs only init'd cur) ----
    cudaStreamWaitEvent(s_int, ev_fork, 0);
    k_intent<<<UB + IB, IT_THREADS, INTENT_SMEM, s_int>>>(Wu, Wi);
    cudaEventRecord(ev_i1, s_int);

    // ---- main: CSR-G build + spmm1 ----
    k_histG<<<12500, 256>>>(G);
    k_scanG1<<<NB_G, 1024>>>();
    k_scanG2<<<1, 32>>>();
    k_scanG3<<<NB_G, 1024>>>();
    k_fillG<<<12500, 256>>>(G, Gv);
    k_spmm_csr<<<9375, 256>>>();
    cudaStreamWaitEvent(0, ev_i1, 0);
    k_epi<<<9375, 256>>>();
    cudaEventRecord(ev_e1, 0);

    // ---- layer 2: spmm on main ∥ intent on s_int ----
    cudaStreamWaitEvent(s_int, ev_e1, 0);
    k_intent<<<UB + IB, IT_THREADS, INTENT_SMEM, s_int>>>(Wu, Wi);
    cudaEventRecord(ev_i2, s_int);
    k_spmm_csr<<<9375, 256>>>();
    cudaStreamWaitEvent(0, ev_i2, 0);
    k_epi<<<9375, 256>>>();

    // ---- join + combine ----
    cudaStreamWaitEvent(0, ev_join, 0);
    k_combine<<<37500, 256>>>(out);
}

// round 14
// speedup vs baseline: 1.5069x; 1.0090x over previous
#include <cuda_runtime.h>

#define NU 100000
#define NI 50000
#define NN 150000
#define DD 64
#define EG 3200000
#define EU_ 1600000
#define EI_ 800000

typedef unsigned long long ull;

// ---------------- device scratch ----------------
__device__ float g_cur[NN * DD];
__device__ float g_gnn[NN * DD];
__device__ float g_int[NN * DD];
__device__ float g_total[NN * DD];
__device__ float g_z[NN * 2 * DD];
__device__ float g_wsum[4];

// CSR for G
__device__ int    g_cntG[NN];
__device__ int    g_curG[NN];
__device__ int    g_rptrG[NN + 1];
__device__ float2 g_epayG[EG];

// CSR + degrees for HAN
#define HN (2 * NU + 2 * NI)
__device__ int g_dout[HN];
__device__ int g_din[HN];
__device__ int g_curH[HN];
__device__ int g_rptrH[2 * (NU + 1) + 2 * (NI + 1)];
__device__ int g_hpay[2 * EU_ + 2 * EI_];

// block-sum scratch for parallel scans
#define NB_G 147
#define NB_HU 98
#define NB_HI 49
__device__ int g_bsumG[NB_G];
__device__ int g_bsumH[4 * NB_HU];

// f32x2 packed math (sm_100+)
__device__ __forceinline__ ull pk2(float a) {
    ull r;
    asm("mov.b64 %0, {%1, %1};" : "=l"(r) : "f"(a));
    return r;
}
__device__ __forceinline__ ull pack2(float lo, float hi) {
    ull r;
    asm("mov.b64 %0, {%1, %2};" : "=l"(r) : "f"(lo), "f"(hi));
    return r;
}
__device__ __forceinline__ void fma2(ull& d, ull a, ull b) {
    asm("fma.rn.f32x2 %0, %1, %2, %0;" : "+l"(d) : "l"(a), "l"(b));
}
__device__ __forceinline__ float2 up2(ull v) {
    float2 f;
    asm("mov.b64 {%0, %1}, %2;" : "=f"(f.x), "=f"(f.y) : "l"(v));
    return f;
}

// ---------------- zero counters ----------------
__global__ void __launch_bounds__(256) k_zero_cnt() {
    unsigned i = blockIdx.x * 256u + threadIdx.x;
    if (i < NN) { g_cntG[i] = 0; g_curG[i] = 0; }
    if (i < HN) { g_dout[i] = 0; g_din[i] = 0; g_curH[i] = 0; }
    if (i < 4u) g_wsum[i] = 0.f;
}

// ---------------- init ----------------
__global__ void __launch_bounds__(256) k_init(const float* __restrict__ fu,
                                              const float* __restrict__ fi) {
    unsigned i = blockIdx.x * 256u + threadIdx.x;
    if (i < NU * DD) {
        float v = fu[i];
        g_cur[i] = v; g_total[i] = v;
    } else if (i < NN * DD) {
        float v = fi[i - NU * DD];
        g_cur[i] = v; g_total[i] = v;
    }
}

// ---------------- histograms ----------------
__global__ void __launch_bounds__(256) k_histG(const int* __restrict__ G) {
    unsigned e = blockIdx.x * 256u + threadIdx.x;
    if (e >= EG) return;
    atomicAdd(&g_cntG[__ldg(G + e)], 1);
}

__global__ void __launch_bounds__(256) k_histH(const int* __restrict__ edges, int E2,
                                               int n, int base) {
    unsigned t = blockIdx.x * 256u + threadIdx.x;
    if (t >= 2u * (unsigned)E2) return;
    int m = (t >= (unsigned)E2) ? 1 : 0;
    int e = (int)t - m * E2;
    int src = __ldg(edges + (size_t)m * 2 * E2 + e);
    int dst = __ldg(edges + (size_t)m * 2 * E2 + E2 + e);
    atomicAdd(&g_dout[base + m * n + src], 1);
    atomicAdd(&g_din[base + m * n + dst], 1);
}

// ---------------- parallel scans ----------------
__device__ __forceinline__ int blockscan_1024(int v, int* ws) {
    const int tid = threadIdx.x, lane = tid & 31, wid = tid >> 5;
    int x = v;
#pragma unroll
    for (int off = 1; off < 32; off <<= 1) {
        int y = __shfl_up_sync(0xffffffffu, x, off);
        if (lane >= off) x += y;
    }
    if (lane == 31) ws[wid] = x;
    __syncthreads();
    if (wid == 0) {
        int s = ws[lane];
#pragma unroll
        for (int off = 1; off < 32; off <<= 1) {
            int y = __shfl_up_sync(0xffffffffu, s, off);
            if (lane >= off) s += y;
        }
        ws[lane] = s;
    }
    __syncthreads();
    return x - v + (wid > 0 ? ws[wid - 1] : 0);
}

__global__ void __launch_bounds__(1024) k_scanG1() {
    __shared__ int ws[32];
    int i = blockIdx.x * 1024 + threadIdx.x;
    int v = (i < NN) ? g_cntG[i] : 0;
    int excl = blockscan_1024(v, ws);
    if (i < NN) g_rptrG[i] = excl;
    if (threadIdx.x == 0) g_bsumG[blockIdx.x] = ws[31];
}

__global__ void __launch_bounds__(32) k_scanG2() {
    int lane = threadIdx.x;
    int carry = 0;
    for (int base = 0; base < NB_G; base += 32) {
        int idx = base + lane;
        int v = (idx < NB_G) ? g_bsumG[idx] : 0;
        int x = v;
#pragma unroll
        for (int off = 1; off < 32; off <<= 1) {
            int y = __shfl_up_sync(0xffffffffu, x, off);
            if (lane >= off) x += y;
        }
        if (idx < NB_G) g_bsumG[idx] = x - v + carry;
        carry += __shfl_sync(0xffffffffu, x, 31);
    }
    if (lane == 0) g_rptrG[NN] = carry;
}

__global__ void __launch_bounds__(1024) k_scanG3() {
    int i = blockIdx.x * 1024 + threadIdx.x;
    if (i < NN) g_rptrG[i] += g_bsumG[blockIdx.x];
}

__device__ __forceinline__ void hseg_decode(int b, int& seg, int& lb, int& n,
                                            const int*& cnt, int*& rptr) {
    if (b < NB_HU)           { seg = 0; lb = b; }
    else if (b < 2 * NB_HU)  { seg = 1; lb = b - NB_HU; }
    else if (b < 2 * NB_HU + NB_HI) { seg = 2; lb = b - 2 * NB_HU; }
    else                     { seg = 3; lb = b - 2 * NB_HU - NB_HI; }
    n = (seg < 2) ? NU : NI;
    cnt = g_din + (seg == 0 ? 0 : seg == 1 ? NU : seg == 2 ? 2 * NU : 2 * NU + NI);
    rptr = g_rptrH + (seg == 0 ? 0 : seg == 1 ? (NU + 1)
                      : seg == 2 ? 2 * (NU + 1) : 2 * (NU + 1) + (NI + 1));
}

__global__ void __launch_bounds__(1024) k_scanH1() {
    __shared__ int ws[32];
    int seg, lb, n; const int* cnt; int* rptr;
    hseg_decode(blockIdx.x, seg, lb, n, cnt, rptr);
    int i = lb * 1024 + threadIdx.x;
    int v = (i < n) ? cnt[i] : 0;
    int excl = blockscan_1024(v, ws);
    if (i < n) rptr[i] = excl;
    if (threadIdx.x == 0) g_bsumH[seg * NB_HU + lb] = ws[31];
}

__global__ void __launch_bounds__(128) k_scanH2() {
    int lane = threadIdx.x & 31, seg = threadIdx.x >> 5;
    int nb = (seg < 2) ? NB_HU : NB_HI;
    int n = (seg < 2) ? NU : NI;
    int* rptr = g_rptrH + (seg == 0 ? 0 : seg == 1 ? (NU + 1)
                           : seg == 2 ? 2 * (NU + 1) : 2 * (NU + 1) + (NI + 1));
    int* bs = g_bsumH + seg * NB_HU;
    int carry = 0;
    for (int base = 0; base < nb; base += 32) {
        int idx = base + lane;
        int v = (idx < nb) ? bs[idx] : 0;
        int x = v;
#pragma unroll
        for (int off = 1; off < 32; off <<= 1) {
            int y = __shfl_up_sync(0xffffffffu, x, off);
            if (lane >= off) x += y;
        }
        if (idx < nb) bs[idx] = x - v + carry;
        carry += __shfl_sync(0xffffffffu, x, 31);
    }
    if (lane == 0) rptr[n] = carry;
}

__global__ void __launch_bounds__(1024) k_scanH3() {
    int seg, lb, n; const int* cnt; int* rptr;
    hseg_decode(blockIdx.x, seg, lb, n, cnt, rptr);
    int i = lb * 1024 + threadIdx.x;
    if (i < n) rptr[i] += g_bsumH[seg * NB_HU + lb];
}

// ---------------- CSR fill ----------------
__global__ void __launch_bounds__(256) k_fillG(const int* __restrict__ G,
                                               const float* __restrict__ gv) {
    unsigned e = blockIdx.x * 256u + threadIdx.x;
    if (e >= EG) return;
    int row = __ldg(G + e);
    int col = __ldg(G + EG + e);
    float v = __ldg(gv + e);
    int pos = g_rptrG[row] + atomicAdd(&g_curG[row], 1);
    g_epayG[pos] = make_float2(__int_as_float(col), v);
}

__global__ void __launch_bounds__(256) k_fillH(const int* __restrict__ edges, int E2,
                                               int n, int base, int rbase, int paybase) {
    unsigned t = blockIdx.x * 256u + threadIdx.x;
    if (t >= 2u * (unsigned)E2) return;
    int m = (t >= (unsigned)E2) ? 1 : 0;
    int e = (int)t - m * E2;
    int src = __ldg(edges + (size_t)m * 2 * E2 + e);
    int dst = __ldg(edges + (size_t)m * 2 * E2 + E2 + e);
    const int* rptr = g_rptrH + rbase + m * (n + 1);
    int pos = rptr[dst] + atomicAdd(&g_curH[base + m * n + dst], 1);
    g_hpay[paybase + m * E2 + pos] = src;
}

// ---------------- DCCF: CSR SpMM ----------------
__global__ void __launch_bounds__(256) k_spmm_csr() {
    unsigned t = blockIdx.x * 256u + threadIdx.x;
    unsigned r = t >> 4;
    unsigned c = t & 15u;
    if (r >= NN) return;
    int s = g_rptrG[r], e = g_rptrG[r + 1];
    float4 acc = make_float4(0.f, 0.f, 0.f, 0.f);
    int i = s;
    for (; i + 2 <= e; i += 2) {
        float2 p0 = __ldg(&g_epayG[i]);
        float2 p1 = __ldg(&g_epayG[i + 1]);
        int c0 = __float_as_int(p0.x), c1 = __float_as_int(p1.x);
        float4 x0 = *(const float4*)(g_cur + (size_t)c0 * DD + c * 4);
        float4 x1 = *(const float4*)(g_cur + (size_t)c1 * DD + c * 4);
        acc.x += p0.y * x0.x + p1.y * x1.x;
        acc.y += p0.y * x0.y + p1.y * x1.y;
        acc.z += p0.y * x0.z + p1.y * x1.z;
        acc.w += p0.y * x0.w + p1.y * x1.w;
    }
    if (i < e) {
        float2 p0 = __ldg(&g_epayG[i]);
        int c0 = __float_as_int(p0.x);
        float4 x0 = *(const float4*)(g_cur + (size_t)c0 * DD + c * 4);
        acc.x += p0.y * x0.x; acc.y += p0.y * x0.y;
        acc.z += p0.y * x0.z; acc.w += p0.y * x0.w;
    }
    *(float4*)(g_gnn + (size_t)r * DD + c * 4) = acc;
}

// ---------------- DCCF: intent projection (src-parameterized, writes g_int) ----------------
#define INTENT_SMEM 82944
#define IT_THREADS 256
#define IT_ROWS_PER_BLOCK 64

__global__ void __launch_bounds__(IT_THREADS, 2)
k_intent(const float* __restrict__ Wu, const float* __restrict__ Wi,
         const float* __restrict__ srcu, const float* __restrict__ srci) {
    extern __shared__ float sm[];
    float2* WTpw = (float2*)sm;
    const float2* WTp = (const float2*)sm;
    const int tid = threadIdx.x, w = tid >> 5, lane = tid & 31;

    ull* uT2 = (ull*)(sm + 8448) + w * 256;
    ull* pT2 = (ull*)(sm + 12544) + w * 512;

    const int UB = (NU + IT_ROWS_PER_BLOCK - 1) / IT_ROWS_PER_BLOCK;
    const bool isUser = (int)blockIdx.x < UB;
    const float* Wg = isUser ? Wu : Wi;
    const int rowbase = isUser ? (int)blockIdx.x * IT_ROWS_PER_BLOCK
                               : NU + ((int)blockIdx.x - UB) * IT_ROWS_PER_BLOCK;
    const int rowlim = isUser ? NU : NN;
    const float* srcp = isUser ? srcu : srci;
    const int srcoff = isUser ? 0 : NU;   // srcp is indexed by (r - srcoff)

    for (int t = tid; t < 4096; t += IT_THREADS) {
        int L = t >> 7, j = t & 127;
        WTpw[j * 33 + L] = make_float2(Wg[(2 * L) * 128 + j], Wg[(2 * L + 1) * 128 + j]);
    }
    __syncthreads();

    const int r0 = rowbase + w * 8;

    for (int t = lane; t < 256; t += 32) {
        int rho = t >> 6, k = t & 63;
        int ra = r0 + 2 * rho, rb = ra + 1;
        float xa = (ra < rowlim) ? srcp[(size_t)(ra - srcoff) * DD + k] : 0.f;
        float xb = (rb < rowlim) ? srcp[(size_t)(rb - srcoff) * DD + k] : 0.f;
        uT2[rho * 64 + k] = pack2(xa, xb);
    }
    __syncwarp();

    ull acc[4][4];
#pragma unroll
    for (int a = 0; a < 4; a++) { acc[a][0] = acc[a][1] = acc[a][2] = acc[a][3] = 0ull; }

    const ulonglong2* uT2v = (const ulonglong2*)uT2;
#pragma unroll 4
    for (int L = 0; L < 32; L++) {
        float2 w0 = WTp[(lane +  0) * 33 + L];
        float2 w1 = WTp[(lane + 32) * 33 + L];
        float2 w2 = WTp[(lane + 64) * 33 + L];
        float2 w3 = WTp[(lane + 96) * 33 + L];
        ull s0x = pk2(w0.x), s0y = pk2(w0.y);
        ull s1x = pk2(w1.x), s1y = pk2(w1.y);
        ull s2x = pk2(w2.x), s2y = pk2(w2.y);
        ull s3x = pk2(w3.x), s3y = pk2(w3.y);
#pragma unroll
        for (int rho = 0; rho < 4; rho++) {
            ulonglong2 up = uT2v[rho * 32 + L];
            fma2(acc[rho][0], s0x, up.x); fma2(acc[rho][0], s0y, up.y);
            fma2(acc[rho][1], s1x, up.x); fma2(acc[rho][1], s1y, up.y);
            fma2(acc[rho][2], s2x, up.x); fma2(acc[rho][2], s2y, up.y);
            fma2(acc[rho][3], s3x, up.x); fma2(acc[rho][3], s3y, up.y);
        }
    }

#pragma unroll
    for (int rho = 0; rho < 4; rho++) {
        float2 a0 = up2(acc[rho][0]), a1 = up2(acc[rho][1]);
        float2 a2 = up2(acc[rho][2]), a3 = up2(acc[rho][3]);
        float ml = fmaxf(fmaxf(a0.x, a1.x), fmaxf(a2.x, a3.x));
        float mh = fmaxf(fmaxf(a0.y, a1.y), fmaxf(a2.y, a3.y));
#pragma unroll
        for (int off = 16; off; off >>= 1) {
            ml = fmaxf(ml, __shfl_xor_sync(0xffffffffu, ml, off));
            mh = fmaxf(mh, __shfl_xor_sync(0xffffffffu, mh, off));
        }
        float el0 = __expf(a0.x - ml), el1 = __expf(a1.x - ml);
        float el2 = __expf(a2.x - ml), el3 = __expf(a3.x - ml);
        float eh0 = __expf(a0.y - mh), eh1 = __expf(a1.y - mh);
        float eh2 = __expf(a2.y - mh), eh3 = __expf(a3.y - mh);
        float sl = el0 + el1 + el2 + el3;
        float sh = eh0 + eh1 + eh2 + eh3;
#pragma unroll
        for (int off = 16; off; off >>= 1) {
            sl += __shfl_xor_sync(0xffffffffu, sl, off);
            sh += __shfl_xor_sync(0xffffffffu, sh, off);
        }
        float il = 1.f / sl, ih = 1.f / sh;
        pT2[rho * 128 + lane +  0] = pack2(el0 * il, eh0 * ih);
        pT2[rho * 128 + lane + 32] = pack2(el1 * il, eh1 * ih);
        pT2[rho * 128 + lane + 64] = pack2(el2 * il, eh2 * ih);
        pT2[rho * 128 + lane + 96] = pack2(el3 * il, eh3 * ih);
    }
    __syncwarp();

    ull acc2[4][2];
#pragma unroll
    for (int a = 0; a < 4; a++) { acc2[a][0] = 0ull; acc2[a][1] = 0ull; }

    const ulonglong2* pT2v = (const ulonglong2*)pT2;
#pragma unroll 2
    for (int j4 = 0; j4 < 32; j4++) {
        ulonglong2 P0a = pT2v[0 * 64 + 2 * j4], P0b = pT2v[0 * 64 + 2 * j4 + 1];
        ulonglong2 P1a = pT2v[1 * 64 + 2 * j4], P1b = pT2v[1 * 64 + 2 * j4 + 1];
        ulonglong2 P2a = pT2v[2 * 64 + 2 * j4], P2b = pT2v[2 * 64 + 2 * j4 + 1];
        ulonglong2 P3a = pT2v[3 * 64 + 2 * j4], P3b = pT2v[3 * 64 + 2 * j4 + 1];
#define P2J(JJ, PW)                                             \
        {                                                       \
            float2 wt = WTp[(4 * j4 + JJ) * 33 + lane];         \
            ull s0 = pk2(wt.x), s1 = pk2(wt.y);                 \
            fma2(acc2[0][0], s0, P0##PW); fma2(acc2[0][1], s1, P0##PW); \
            fma2(acc2[1][0], s0, P1##PW); fma2(acc2[1][1], s1, P1##PW); \
            fma2(acc2[2][0], s0, P2##PW); fma2(acc2[2][1], s1, P2##PW); \
            fma2(acc2[3][0], s0, P3##PW); fma2(acc2[3][1], s1, P3##PW); \
        }
        P2J(0, a.x) P2J(1, a.y) P2J(2, b.x) P2J(3, b.y)
#undef P2J
    }

#pragma unroll
    for (int rho = 0; rho < 4; rho++) {
        float2 o0 = up2(acc2[rho][0]);
        float2 o1 = up2(acc2[rho][1]);
#pragma unroll
        for (int par = 0; par < 2; par++) {
            int r = r0 + 2 * rho + par;
            if (r >= rowlim) continue;
            float oa = par ? o0.y : o0.x;
            float ob = par ? o1.y : o1.x;
            *(float2*)(g_int + (size_t)r * DD + lane * 2) = make_float2(oa, ob);
        }
    }
}

// ---------------- DCCF: layer epilogue ----------------
__global__ void __launch_bounds__(256) k_epi() {
    unsigned i = blockIdx.x * 256u + threadIdx.x;
    if (i >= (unsigned)(NN * DD / 4)) return;
    float4 gn = ((const float4*)g_gnn)[i];
    float4 iv = ((const float4*)g_int)[i];
    float4 cu = ((const float4*)g_cur)[i];
    float4 tt = ((const float4*)g_total)[i];
    float4 nv;
    nv.x = gn.x + iv.x + cu.x;
    nv.y = gn.y + iv.y + cu.y;
    nv.z = gn.z + iv.z + cu.z;
    nv.w = gn.w + iv.w + cu.w;
    ((float4*)g_cur)[i] = nv;
    tt.x += nv.x; tt.y += nv.y; tt.z += nv.z; tt.w += nv.w;
    ((float4*)g_total)[i] = tt;
}

// ---------------- HAN: CSR gather ----------------
__global__ void __launch_bounds__(256) k_hgather(const float* __restrict__ feat, int E2,
                                                 int n, int base, int rbase, int paybase,
                                                 int zbase) {
    unsigned t = blockIdx.x * 256u + threadIdx.x;
    unsigned idx = t >> 4;
    unsigned c = t & 15u;
    if (idx >= 2u * (unsigned)n) return;
    int m = (idx >= (unsigned)n) ? 1 : 0;
    int node = (int)idx - m * n;
    const int* rptr = g_rptrH + rbase + m * (n + 1);
    int s = rptr[node], e = rptr[node + 1];
    const int* pay = g_hpay + paybase + m * E2;
    const int* dout = g_dout + base + m * n;
    float4 acc = make_float4(0.f, 0.f, 0.f, 0.f);
    int i = s;
    for (; i + 2 <= e; i += 2) {
        int s0 = __ldg(pay + i), s1 = __ldg(pay + i + 1);
        float w0 = rsqrtf((float)__ldg(dout + s0));
        float w1 = rsqrtf((float)__ldg(dout + s1));
        float4 x0 = *(const float4*)(feat + (size_t)s0 * DD + c * 4);
        float4 x1 = *(const float4*)(feat + (size_t)s1 * DD + c * 4);
        acc.x += w0 * x0.x + w1 * x1.x;
        acc.y += w0 * x0.y + w1 * x1.y;
        acc.z += w0 * x0.z + w1 * x1.z;
        acc.w += w0 * x0.w + w1 * x1.w;
    }
    if (i < e) {
        int s0 = __ldg(pay + i);
        float w0 = rsqrtf((float)__ldg(dout + s0));
        float4 x0 = *(const float4*)(feat + (size_t)s0 * DD + c * 4);
        acc.x += w0 * x0.x; acc.y += w0 * x0.y;
        acc.z += w0 * x0.z; acc.w += w0 * x0.w;
    }
    float din = (float)(e - s);
    float sc = (din > 0.f) ? rsqrtf(din) : 0.f;
    *(float4*)(g_z + (size_t)zbase + ((size_t)node * 2 + m) * DD + c * 4) =
        make_float4(acc.x * sc, acc.y * sc, acc.z * sc, acc.w * sc);
}

// ---------------- HAN: semantic attention logits ----------------
__global__ void __launch_bounds__(256) k_han_node(const float* __restrict__ W1g,
                                                  const float* __restrict__ b1g,
                                                  const float* __restrict__ w2g,
                                                  int n, int zbase, int wbase) {
    __shared__ float Wsm[8192];
    __shared__ float ush[4096];
    __shared__ float bsh[128];
    __shared__ float w2sh[128];
    __shared__ float wacc[2];

    const int tid = threadIdx.x, w = tid >> 5, lane = tid & 31;
    for (int t = tid; t < 2048; t += 256) {
        int k = t >> 5, L = t & 31;
        ((float4*)Wsm)[t] = *(const float4*)(W1g + k * 128 + L * 4);
    }
    if (tid < 128) { bsh[tid] = b1g[tid]; w2sh[tid] = w2g[tid]; }
    if (tid < 2) wacc[tid] = 0.f;
    __syncthreads();

    const int rows = 2 * n;
    const int r0 = (int)blockIdx.x * 64 + w * 8;
    float* u = ush + w * 512;

    for (int t = lane; t < 512; t += 32) {
        int rr = t >> 6, d = t & 63;
        int row = r0 + rr;
        u[t] = (row < rows) ? g_z[(size_t)zbase + (size_t)row * DD + d] : 0.f;
    }
    __syncwarp();

    float acc[8][4];
#pragma unroll
    for (int a = 0; a < 8; a++) { acc[a][0] = acc[a][1] = acc[a][2] = acc[a][3] = 0.f; }

#pragma unroll 2
    for (int kk = 0; kk < 16; kk++) {
        float4 w0 = ((const float4*)Wsm)[(4 * kk + 0) * 32 + lane];
        float4 w1 = ((const float4*)Wsm)[(4 * kk + 1) * 32 + lane];
        float4 w2 = ((const float4*)Wsm)[(4 * kk + 2) * 32 + lane];
        float4 w3 = ((const float4*)Wsm)[(4 * kk + 3) * 32 + lane];
#pragma unroll
        for (int rr = 0; rr < 8; rr++) {
            float4 uv = *(const float4*)(u + rr * 64 + kk * 4);
            acc[rr][0] += uv.x * w0.x + uv.y * w1.x + uv.z * w2.x + uv.w * w3.x;
            acc[rr][1] += uv.x * w0.y + uv.y * w1.y + uv.z * w2.y + uv.w * w3.y;
            acc[rr][2] += uv.x * w0.z + uv.y * w1.z + uv.z * w2.z + uv.w * w3.z;
            acc[rr][3] += uv.x * w0.w + uv.y * w1.w + uv.z * w2.w + uv.w * w3.w;
        }
    }

    float wl01[2] = {0.f, 0.f};
#pragma unroll
    for (int rr = 0; rr < 8; rr++) {
        int row = r0 + rr;
        float wl = 0.f;
#pragma unroll
        for (int c = 0; c < 4; c++) {
            int j = lane * 4 + c;
            wl += tanhf(acc[rr][c] + bsh[j]) * w2sh[j];
        }
        if (row < rows) wl01[row & 1] += wl;
    }
#pragma unroll
    for (int off = 16; off; off >>= 1) {
        wl01[0] += __shfl_xor_sync(0xffffffffu, wl01[0], off);
        wl01[1] += __shfl_xor_sync(0xffffffffu, wl01[1], off);
    }
    if (lane == 0) {
        atomicAdd(&wacc[0], wl01[0]);
        atomicAdd(&wacc[1], wl01[1]);
    }
    __syncthreads();
    if (tid < 2) atomicAdd(&g_wsum[wbase + tid], wacc[tid]);
}

// ---------------- final combine ----------------
__global__ void __launch_bounds__(256) k_combine(float* __restrict__ out) {
    unsigned i = blockIdx.x * 256u + threadIdx.x;
    if (i >= (unsigned)(NN * DD)) return;
    unsigned node = i >> 6, d = i & 63u;
    float w0, w1;
    size_t zr;
    if (node < NU) {
        w0 = g_wsum[0] * (1.f / NU);
        w1 = g_wsum[1] * (1.f / NU);
        zr = (size_t)node * 128;
    } else {
        w0 = g_wsum[2] * (1.f / NI);
        w1 = g_wsum[3] * (1.f / NI);
        zr = (size_t)NU * 128 + (size_t)(node - NU) * 128;
    }
    float mx = fmaxf(w0, w1);
    float e0 = __expf(w0 - mx), e1 = __expf(w1 - mx);
    float inv = 1.f / (e0 + e1);
    float han = (e0 * inv) * g_z[zr + d] + (e1 * inv) * g_z[zr + 64 + d];
    out[i] = 0.5f * g_total[i] + 0.5f * han;
}

// ---------------- launcher: legal capture fork via root event ----------------
extern "C" void kernel_launch(void* const* d_in, const int* in_sizes, int n_in,
                              void* d_out, int out_size) {
    const int*   G    = (const int*)d_in[0];
    const float* Gv   = (const float*)d_in[1];
    const float* fu   = (const float*)d_in[2];
    const float* fi   = (const float*)d_in[3];
    const float* Wu   = (const float*)d_in[4];
    const float* Wi   = (const float*)d_in[5];
    const int*   eu   = (const int*)d_in[6];
    const int*   ei   = (const int*)d_in[7];
    const float* suW1 = (const float*)d_in[8];
    const float* sub1 = (const float*)d_in[9];
    const float* suw2 = (const float*)d_in[10];
    const float* siW1 = (const float*)d_in[11];
    const float* sib1 = (const float*)d_in[12];
    const float* siw2 = (const float*)d_in[13];
    float* out = (float*)d_out;

    static cudaStream_t s_han = nullptr, s_int = nullptr, s_init = nullptr;
    static cudaEvent_t ev_root = nullptr, ev_zero = nullptr, ev_join = nullptr;
    static cudaEvent_t ev_init = nullptr, ev_i1 = nullptr, ev_i2 = nullptr, ev_e1 = nullptr;
    static float* p_cur = nullptr;
    if (!s_han) {
        cudaStreamCreateWithFlags(&s_han, cudaStreamNonBlocking);
        cudaStreamCreateWithFlags(&s_int, cudaStreamNonBlocking);
        cudaStreamCreateWithFlags(&s_init, cudaStreamNonBlocking);
        cudaEventCreateWithFlags(&ev_root, cudaEventDisableTiming);
        cudaEventCreateWithFlags(&ev_zero, cudaEventDisableTiming);
        cudaEventCreateWithFlags(&ev_join, cudaEventDisableTiming);
        cudaEventCreateWithFlags(&ev_init, cudaEventDisableTiming);
        cudaEventCreateWithFlags(&ev_i1, cudaEventDisableTiming);
        cudaEventCreateWithFlags(&ev_i2, cudaEventDisableTiming);
        cudaEventCreateWithFlags(&ev_e1, cudaEventDisableTiming);
        cudaFuncSetAttribute(k_intent, cudaFuncAttributeMaxDynamicSharedMemorySize,
                             INTENT_SMEM);
        cudaGetSymbolAddress((void**)&p_cur, g_cur);
    }

    const int UB = (NU + IT_ROWS_PER_BLOCK - 1) / IT_ROWS_PER_BLOCK;
    const int IB = (NI + IT_ROWS_PER_BLOCK - 1) / IT_ROWS_PER_BLOCK;

    // root fork on the capture stream (must precede any side-stream work)
    cudaEventRecord(ev_root, 0);

    // ---- layer-1 intent on s_int: reads fu/fi directly, starts at t~0 ----
    cudaStreamWaitEvent(s_int, ev_root, 0);
    k_intent<<<UB + IB, IT_THREADS, INTENT_SMEM, s_int>>>(Wu, Wi, fu, fi);
    cudaEventRecord(ev_i1, s_int);

    // ---- init on its own stream ----
    cudaStreamWaitEvent(s_init, ev_root, 0);
    k_init<<<37500, 256, 0, s_init>>>(fu, fi);
    cudaEventRecord(ev_init, s_init);

    // ---- main: counters zero, then fork HAN ----
    k_zero_cnt<<<1172, 256>>>();
    cudaEventRecord(ev_zero, 0);

    cudaStreamWaitEvent(s_han, ev_zero, 0);
    k_histH<<<12500, 256, 0, s_han>>>(eu, EU_, NU, 0);
    k_histH<<<6250, 256, 0, s_han>>>(ei, EI_, NI, 2 * NU);
    k_scanH1<<<2 * NB_HU + 2 * NB_HI, 1024, 0, s_han>>>();
    k_scanH2<<<1, 128, 0, s_han>>>();
    k_scanH3<<<2 * NB_HU + 2 * NB_HI, 1024, 0, s_han>>>();
    k_fillH<<<12500, 256, 0, s_han>>>(eu, EU_, NU, 0, 0, 0);
    k_fillH<<<6250, 256, 0, s_han>>>(ei, EI_, NI, 2 * NU, 2 * (NU + 1), 2 * EU_);
    k_hgather<<<12500, 256, 0, s_han>>>(fu, EU_, NU, 0, 0, 0, 0);
    k_hgather<<<6250, 256, 0, s_han>>>(fi, EI_, NI, 2 * NU, 2 * (NU + 1), 2 * EU_, NU * 128);
    k_han_node<<<3125, 256, 0, s_han>>>(suW1, sub1, suw2, NU, 0, 0);
    k_han_node<<<1563, 256, 0, s_han>>>(siW1, sib1, siw2, NI, NU * 128, 2);
    cudaEventRecord(ev_join, s_han);

    // ---- main: CSR-G build + spmm1 ----
    k_histG<<<12500, 256>>>(G);
    k_scanG1<<<NB_G, 1024>>>();
    k_scanG2<<<1, 32>>>();
    k_scanG3<<<NB_G, 1024>>>();
    k_fillG<<<12500, 256>>>(G, Gv);
    cudaStreamWaitEvent(0, ev_init, 0);
    k_spmm_csr<<<9375, 256>>>();
    cudaStreamWaitEvent(0, ev_i1, 0);
    k_epi<<<9375, 256>>>();
    cudaEventRecord(ev_e1, 0);

    // ---- layer 2: spmm on main ∥ intent on s_int ----
    cudaStreamWaitEvent(s_int, ev_e1, 0);
    k_intent<<<UB + IB, IT_THREADS, INTENT_SMEM, s_int>>>(
        Wu, Wi, p_cur, p_cur + (size_t)NU * DD);   // item src offset FIX
    cudaEventRecord(ev_i2, s_int);
    k_spmm_csr<<<9375, 256>>>();
    cudaStreamWaitEvent(0, ev_i2, 0);
    k_epi<<<9375, 256>>>();

    // ---- join + combine ----
    cudaStreamWaitEvent(0, ev_join, 0);
    k_combine<<<37500, 256>>>(out);
}